// round 1
// baseline (speedup 1.0000x reference)
#include <cuda_runtime.h>

#define B_    4
#define SEQ   2048
#define DM    1024
#define NH    16
#define HD    64
#define NTOK  (B_*SEQ)          // 8192

// Scratch (allocation-free rule: __device__ globals)
__device__ float g_Q[B_*NH*SEQ*HD];   // [b,h,n,d]
__device__ float g_K[B_*NH*SEQ*HD];
__device__ float g_V[B_*NH*SEQ*HD];
__device__ float g_ctx[NTOK*DM];      // [b*n, D]

// ---------------------------------------------------------------------------
// QKV projection GEMM: out = x @ W, scattered to [b,h,n,d]
// 64x64 tile, BK=32, 256 threads, 4x4 per thread
// ---------------------------------------------------------------------------
__global__ __launch_bounds__(256) void qkv_gemm_kernel(
    const float* __restrict__ x,
    const float* __restrict__ Wq,
    const float* __restrict__ Wk,
    const float* __restrict__ Wv)
{
    const float* W      = (blockIdx.z == 0) ? Wq : (blockIdx.z == 1) ? Wk : Wv;
    float*       outbuf = (blockIdx.z == 0) ? g_Q : (blockIdx.z == 1) ? g_K : g_V;

    __shared__ float As[64][33];   // [m][k], padded
    __shared__ float Bs[32][64];   // [k][n]

    const int row0 = blockIdx.y * 64;
    const int col0 = blockIdx.x * 64;
    const int tid  = threadIdx.x;
    const int tx   = tid & 15;
    const int ty   = tid >> 4;

    float acc[4][4] = {};

    for (int k0 = 0; k0 < DM; k0 += 32) {
        #pragma unroll
        for (int t = 0; t < 8; t++) {
            int i = tid + t * 256;           // 0..2047
            int m = i >> 5, kk = i & 31;     // coalesced over kk
            As[m][kk] = x[(row0 + m) * DM + k0 + kk];
        }
        #pragma unroll
        for (int t = 0; t < 8; t++) {
            int i = tid + t * 256;
            int kk = i >> 6, c = i & 63;     // coalesced over c
            Bs[kk][c] = W[(k0 + kk) * DM + col0 + c];
        }
        __syncthreads();

        #pragma unroll
        for (int kk = 0; kk < 32; kk++) {
            float a[4], b[4];
            #pragma unroll
            for (int i = 0; i < 4; i++) a[i] = As[ty * 4 + i][kk];
            #pragma unroll
            for (int j = 0; j < 4; j++) b[j] = Bs[kk][tx * 4 + j];
            #pragma unroll
            for (int i = 0; i < 4; i++)
                #pragma unroll
                for (int j = 0; j < 4; j++)
                    acc[i][j] += a[i] * b[j];
        }
        __syncthreads();
    }

    #pragma unroll
    for (int i = 0; i < 4; i++) {
        int gr = row0 + ty * 4 + i;
        int bb = gr / SEQ, n = gr % SEQ;
        #pragma unroll
        for (int j = 0; j < 4; j++) {
            int gc = col0 + tx * 4 + j;
            int h = gc >> 6, d = gc & 63;
            outbuf[(((bb * NH + h) * SEQ) + n) * HD + d] = acc[i][j];
        }
    }
}

// ---------------------------------------------------------------------------
// Flash attention (causal), fp32. Block: 256 threads, 64-query tile.
// 4 threads per query row, each owns 16 of the 64 head dims.
// K/V tiles (64x64 fp32 each, contiguous in [b,h,n,d]) staged in smem.
// ---------------------------------------------------------------------------
__global__ __launch_bounds__(256) void flash_kernel()
{
    const int qt = blockIdx.x;   // 0..31
    const int h  = blockIdx.y;
    const int b  = blockIdx.z;

    const float* Q = g_Q + (size_t)((b * NH + h) * SEQ) * HD;
    const float* K = g_K + (size_t)((b * NH + h) * SEQ) * HD;
    const float* V = g_V + (size_t)((b * NH + h) * SEQ) * HD;

    __shared__ float Ks[64 * 64];
    __shared__ float Vs[64 * 64];

    const int tid  = threadIdx.x;
    const int r    = tid >> 2;        // query row within tile
    const int quad = tid & 3;         // which 16 dims
    const int q0   = qt * 64;

    float q[16], acc[16];
    #pragma unroll
    for (int d = 0; d < 16; d++) {
        q[d]   = Q[(q0 + r) * HD + quad * 16 + d];
        acc[d] = 0.f;
    }
    float m = -1e30f, l = 0.f;
    float s[64];

    for (int kt = 0; kt <= qt; kt++) {
        const int k0 = kt * 64;
        // K/V tile is a contiguous 4096-float chunk
        const float4* Kg = (const float4*)(K + (size_t)k0 * HD);
        const float4* Vg = (const float4*)(V + (size_t)k0 * HD);
        float4* Ks4 = (float4*)Ks;
        float4* Vs4 = (float4*)Vs;
        #pragma unroll
        for (int t = 0; t < 4; t++) {
            Ks4[tid + t * 256] = Kg[tid + t * 256];
            Vs4[tid + t * 256] = Vg[tid + t * 256];
        }
        __syncthreads();

        // scores for this tile
        float tilemax = -1e30f;
        const bool diag = (kt == qt);
        #pragma unroll
        for (int j = 0; j < 64; j++) {
            const float* kr = Ks + j * 64 + quad * 16;
            float p = 0.f;
            #pragma unroll
            for (int d = 0; d < 16; d++) p += q[d] * kr[d];
            p += __shfl_xor_sync(0xffffffffu, p, 1);
            p += __shfl_xor_sync(0xffffffffu, p, 2);
            p = (diag && j > r) ? -1e30f : p * 0.125f;
            s[j] = p;
            tilemax = fmaxf(tilemax, p);
        }

        float newm = fmaxf(m, tilemax);
        float corr = __expf(m - newm);
        l *= corr;
        #pragma unroll
        for (int d = 0; d < 16; d++) acc[d] *= corr;

        #pragma unroll
        for (int j = 0; j < 64; j++) {
            float p = __expf(s[j] - newm);
            l += p;
            const float* vr = Vs + j * 64 + quad * 16;
            #pragma unroll
            for (int d = 0; d < 16; d++) acc[d] += p * vr[d];
        }
        m = newm;
        __syncthreads();
    }

    const float inv = 1.f / l;
    float* o = g_ctx + (size_t)(b * SEQ + q0 + r) * DM + h * HD + quad * 16;
    #pragma unroll
    for (int d = 0; d < 16; d++) o[d] = acc[d] * inv;
}

// ---------------------------------------------------------------------------
// Output projection: d_out = ctx @ Wo + bo
// ---------------------------------------------------------------------------
__global__ __launch_bounds__(256) void out_gemm_kernel(
    const float* __restrict__ Wo,
    const float* __restrict__ bo,
    float* __restrict__ out)
{
    __shared__ float As[64][33];
    __shared__ float Bs[32][64];

    const int row0 = blockIdx.y * 64;
    const int col0 = blockIdx.x * 64;
    const int tid  = threadIdx.x;
    const int tx   = tid & 15;
    const int ty   = tid >> 4;

    float acc[4][4] = {};

    for (int k0 = 0; k0 < DM; k0 += 32) {
        #pragma unroll
        for (int t = 0; t < 8; t++) {
            int i = tid + t * 256;
            int m = i >> 5, kk = i & 31;
            As[m][kk] = g_ctx[(size_t)(row0 + m) * DM + k0 + kk];
        }
        #pragma unroll
        for (int t = 0; t < 8; t++) {
            int i = tid + t * 256;
            int kk = i >> 6, c = i & 63;
            Bs[kk][c] = Wo[(k0 + kk) * DM + col0 + c];
        }
        __syncthreads();

        #pragma unroll
        for (int kk = 0; kk < 32; kk++) {
            float a[4], b[4];
            #pragma unroll
            for (int i = 0; i < 4; i++) a[i] = As[ty * 4 + i][kk];
            #pragma unroll
            for (int j = 0; j < 4; j++) b[j] = Bs[kk][tx * 4 + j];
            #pragma unroll
            for (int i = 0; i < 4; i++)
                #pragma unroll
                for (int j = 0; j < 4; j++)
                    acc[i][j] += a[i] * b[j];
        }
        __syncthreads();
    }

    #pragma unroll
    for (int i = 0; i < 4; i++) {
        int gr = row0 + ty * 4 + i;
        #pragma unroll
        for (int j = 0; j < 4; j++) {
            int gc = col0 + tx * 4 + j;
            out[(size_t)gr * DM + gc] = acc[i][j] + bo[gc];
        }
    }
}

// ---------------------------------------------------------------------------
extern "C" void kernel_launch(void* const* d_in, const int* in_sizes, int n_in,
                              void* d_out, int out_size)
{
    const float* x  = (const float*)d_in[0];
    const float* Wq = (const float*)d_in[1];
    const float* Wk = (const float*)d_in[2];
    const float* Wv = (const float*)d_in[3];
    const float* Wo = (const float*)d_in[4];
    const float* bo = (const float*)d_in[5];
    float* out = (float*)d_out;

    dim3 g1(DM / 64, NTOK / 64, 3);        // 16 x 128 x 3
    qkv_gemm_kernel<<<g1, 256>>>(x, Wq, Wk, Wv);

    dim3 g2(SEQ / 64, NH, B_);             // 32 x 16 x 4
    flash_kernel<<<g2, 256>>>();

    dim3 g3(DM / 64, NTOK / 64);           // 16 x 128
    out_gemm_kernel<<<g3, 256>>>(Wo, bo, out);
}

// round 7
// speedup vs baseline: 1.0537x; 1.0537x over previous
#include <cuda_runtime.h>
#include <cstdint>

#define B_    4
#define SEQ   2048
#define DM    1024
#define NH    16
#define HD    64
#define NTOK  (B_*SEQ)          // 8192

// ---------------------------------------------------------------------------
// Device scratch (allocation-free rule)
// ---------------------------------------------------------------------------
__device__ float g_Q[B_*NH*SEQ*HD];   // [b,h,n,d]
__device__ float g_K[B_*NH*SEQ*HD];
__device__ float g_V[B_*NH*SEQ*HD];
__device__ float g_ctx[NTOK*DM];      // [token, D]
__device__ float g_WoT[DM*DM];        // Wo transposed: [n][k]

// ---------------------------------------------------------------------------
__device__ __forceinline__ uint32_t f2tf32(float x) {
    uint32_t u;
    asm("cvt.rna.tf32.f32 %0, %1;" : "=r"(u) : "f"(x));
    return u;
}

__device__ __forceinline__ void mma_tf32(float* d, const uint32_t* a,
                                         uint32_t b0, uint32_t b1) {
    asm volatile(
        "mma.sync.aligned.m16n8k8.row.col.f32.tf32.tf32.f32 "
        "{%0,%1,%2,%3}, {%4,%5,%6,%7}, {%8,%9}, {%0,%1,%2,%3};"
        : "+f"(d[0]), "+f"(d[1]), "+f"(d[2]), "+f"(d[3])
        : "r"(a[0]), "r"(a[1]), "r"(a[2]), "r"(a[3]), "r"(b0), "r"(b1));
}

// ---------------------------------------------------------------------------
// QKV projection GEMM — round-1 validated, byte-identical.
// ---------------------------------------------------------------------------
__global__ __launch_bounds__(256) void qkv_gemm_kernel(
    const float* __restrict__ x,
    const float* __restrict__ Wq,
    const float* __restrict__ Wk,
    const float* __restrict__ Wv)
{
    const float* W      = (blockIdx.z == 0) ? Wq : (blockIdx.z == 1) ? Wk : Wv;
    float*       outbuf = (blockIdx.z == 0) ? g_Q : (blockIdx.z == 1) ? g_K : g_V;

    __shared__ float As[64][33];   // [m][k], padded
    __shared__ float Bs[32][64];   // [k][n]

    const int row0 = blockIdx.y * 64;
    const int col0 = blockIdx.x * 64;
    const int tid  = threadIdx.x;
    const int tx   = tid & 15;
    const int ty   = tid >> 4;

    float acc[4][4] = {};

    for (int k0 = 0; k0 < DM; k0 += 32) {
        #pragma unroll
        for (int t = 0; t < 8; t++) {
            int i = tid + t * 256;           // 0..2047
            int m = i >> 5, kk = i & 31;     // coalesced over kk
            As[m][kk] = x[(row0 + m) * DM + k0 + kk];
        }
        #pragma unroll
        for (int t = 0; t < 8; t++) {
            int i = tid + t * 256;
            int kk = i >> 6, c = i & 63;     // coalesced over c
            Bs[kk][c] = W[(k0 + kk) * DM + col0 + c];
        }
        __syncthreads();

        #pragma unroll
        for (int kk = 0; kk < 32; kk++) {
            float a[4], b[4];
            #pragma unroll
            for (int i = 0; i < 4; i++) a[i] = As[ty * 4 + i][kk];
            #pragma unroll
            for (int j = 0; j < 4; j++) b[j] = Bs[kk][tx * 4 + j];
            #pragma unroll
            for (int i = 0; i < 4; i++)
                #pragma unroll
                for (int j = 0; j < 4; j++)
                    acc[i][j] += a[i] * b[j];
        }
        __syncthreads();
    }

    #pragma unroll
    for (int i = 0; i < 4; i++) {
        int gr = row0 + ty * 4 + i;
        int bb = gr / SEQ, n = gr % SEQ;
        #pragma unroll
        for (int j = 0; j < 4; j++) {
            int gc = col0 + tx * 4 + j;
            int h = gc >> 6, d = gc & 63;
            outbuf[(((bb * NH + h) * SEQ) + n) * HD + d] = acc[i][j];
        }
    }
}

// ---------------------------------------------------------------------------
// Wo transpose: g_WoT[n][k] = Wo[k][n]
// ---------------------------------------------------------------------------
__global__ __launch_bounds__(256) void transpose_wo(const float* __restrict__ Wo)
{
    __shared__ float t[32][33];
    int tx = threadIdx.x, ty = threadIdx.y;
    int x0 = blockIdx.x * 32, y0 = blockIdx.y * 32;
    #pragma unroll
    for (int j = ty; j < 32; j += 8)
        t[j][tx] = Wo[(size_t)(y0 + j) * DM + x0 + tx];
    __syncthreads();
    #pragma unroll
    for (int j = ty; j < 32; j += 8)
        g_WoT[(size_t)(x0 + j) * DM + y0 + tx] = t[tx][j];
}

// ---------------------------------------------------------------------------
// Flash attention (causal), fp32 — round-1 validated, byte-identical.
// ---------------------------------------------------------------------------
__global__ __launch_bounds__(256) void flash_kernel()
{
    const int qt = blockIdx.x;
    const int h  = blockIdx.y;
    const int b  = blockIdx.z;

    const float* Q = g_Q + (size_t)((b * NH + h) * SEQ) * HD;
    const float* K = g_K + (size_t)((b * NH + h) * SEQ) * HD;
    const float* V = g_V + (size_t)((b * NH + h) * SEQ) * HD;

    __shared__ float Ks[64 * 64];
    __shared__ float Vs[64 * 64];

    const int tid  = threadIdx.x;
    const int r    = tid >> 2;
    const int quad = tid & 3;
    const int q0   = qt * 64;

    float q[16], acc[16];
    #pragma unroll
    for (int d = 0; d < 16; d++) {
        q[d]   = Q[(q0 + r) * HD + quad * 16 + d];
        acc[d] = 0.f;
    }
    float m = -1e30f, l = 0.f;
    float s[64];

    for (int kt = 0; kt <= qt; kt++) {
        const int k0 = kt * 64;
        const float4* Kg = (const float4*)(K + (size_t)k0 * HD);
        const float4* Vg = (const float4*)(V + (size_t)k0 * HD);
        float4* Ks4 = (float4*)Ks;
        float4* Vs4 = (float4*)Vs;
        #pragma unroll
        for (int t = 0; t < 4; t++) {
            Ks4[tid + t * 256] = Kg[tid + t * 256];
            Vs4[tid + t * 256] = Vg[tid + t * 256];
        }
        __syncthreads();

        float tilemax = -1e30f;
        const bool diag = (kt == qt);
        #pragma unroll
        for (int j = 0; j < 64; j++) {
            const float* kr = Ks + j * 64 + quad * 16;
            float p = 0.f;
            #pragma unroll
            for (int d = 0; d < 16; d++) p += q[d] * kr[d];
            p += __shfl_xor_sync(0xffffffffu, p, 1);
            p += __shfl_xor_sync(0xffffffffu, p, 2);
            p = (diag && j > r) ? -1e30f : p * 0.125f;
            s[j] = p;
            tilemax = fmaxf(tilemax, p);
        }

        float newm = fmaxf(m, tilemax);
        float corr = __expf(m - newm);
        l *= corr;
        #pragma unroll
        for (int d = 0; d < 16; d++) acc[d] *= corr;

        #pragma unroll
        for (int j = 0; j < 64; j++) {
            float p = __expf(s[j] - newm);
            l += p;
            const float* vr = Vs + j * 64 + quad * 16;
            #pragma unroll
            for (int d = 0; d < 16; d++) acc[d] += p * vr[d];
        }
        m = newm;
        __syncthreads();
    }

    const float inv = 1.f / l;
    float* o = g_ctx + (size_t)(b * SEQ + q0 + r) * DM + h * HD + quad * 16;
    #pragma unroll
    for (int d = 0; d < 16; d++) o[d] = acc[d] * inv;
}

// ---------------------------------------------------------------------------
// Out-projection via tf32 mma.sync (isolated test of the mma machinery).
// C[128x128] = g_ctx[128xK] @ WoT[128xK]^T + bias,  K=1024, BK=32.
// Smem swizzle: addr(m,k) = m*32 + ((k>>2)^(m&7))*4 + (k&3)
// Fragments per CUTLASS SM80_16x8x8_F32TF32TF32F32_TN traits.
// ---------------------------------------------------------------------------
__global__ __launch_bounds__(256, 2) void out_mma(
    const float* __restrict__ bias,
    float* __restrict__ Cout)
{
    __shared__ __align__(16) uint32_t sA[128 * 32];
    __shared__ __align__(16) uint32_t sB[128 * 32];

    const int tid   = threadIdx.x;
    const int lane  = tid & 31;
    const int wid   = tid >> 5;
    const int warpM = wid & 1;
    const int warpN = wid >> 1;
    const int row0  = blockIdx.y * 128;
    const int col0  = blockIdx.x * 128;

    const int cm  = tid >> 3;
    const int ckq = tid & 7;
    const int g   = lane >> 2;
    const int t4  = lane & 3;

    float acc[4][4][4] = {};

    for (int c = 0; c < DM / 32; c++) {
        const int kbase = c * 32 + ckq * 4;
        #pragma unroll
        for (int t = 0; t < 4; t++) {
            int m = cm + t * 32;
            float4 va = *(const float4*)&g_ctx[(size_t)(row0 + m) * DM + kbase];
            float4 vb = *(const float4*)&g_WoT[(size_t)(col0 + m) * DM + kbase];
            uint32_t off = (uint32_t)(m * 32 + ((ckq ^ (m & 7)) << 2));
            uint4 ua = { f2tf32(va.x), f2tf32(va.y), f2tf32(va.z), f2tf32(va.w) };
            uint4 ub = { f2tf32(vb.x), f2tf32(vb.y), f2tf32(vb.z), f2tf32(vb.w) };
            *(uint4*)&sA[off] = ua;
            *(uint4*)&sB[off] = ub;
        }
        __syncthreads();

        #pragma unroll
        for (int kb = 0; kb < 4; kb++) {
            const int qlo = ((kb * 2 + 0) ^ g) << 2;
            const int qhi = ((kb * 2 + 1) ^ g) << 2;

            uint32_t a[4][4];
            #pragma unroll
            for (int mf = 0; mf < 4; mf++) {
                int mr = warpM * 64 + mf * 16;
                a[mf][0] = sA[(mr + g)     * 32 + qlo + t4];
                a[mf][1] = sA[(mr + 8 + g) * 32 + qlo + t4];
                a[mf][2] = sA[(mr + g)     * 32 + qhi + t4];
                a[mf][3] = sA[(mr + 8 + g) * 32 + qhi + t4];
            }
            uint32_t b[4][2];
            #pragma unroll
            for (int nf = 0; nf < 4; nf++) {
                int nr = warpN * 32 + nf * 8 + g;
                b[nf][0] = sB[nr * 32 + qlo + t4];
                b[nf][1] = sB[nr * 32 + qhi + t4];
            }
            #pragma unroll
            for (int mf = 0; mf < 4; mf++)
                #pragma unroll
                for (int nf = 0; nf < 4; nf++)
                    mma_tf32(acc[mf][nf], a[mf], b[nf][0], b[nf][1]);
        }
        __syncthreads();
    }

    #pragma unroll
    for (int mf = 0; mf < 4; mf++) {
        #pragma unroll
        for (int half = 0; half < 2; half++) {
            int gr = row0 + warpM * 64 + mf * 16 + g + half * 8;
            #pragma unroll
            for (int nf = 0; nf < 4; nf++) {
                int gc = col0 + warpN * 32 + nf * 8 + t4 * 2;
                float2 bv = *(const float2*)&bias[gc];
                *(float2*)&Cout[(size_t)gr * DM + gc]
                    = make_float2(acc[mf][nf][half * 2 + 0] + bv.x,
                                  acc[mf][nf][half * 2 + 1] + bv.y);
            }
        }
    }
}

// ---------------------------------------------------------------------------
extern "C" void kernel_launch(void* const* d_in, const int* in_sizes, int n_in,
                              void* d_out, int out_size)
{
    const float* x  = (const float*)d_in[0];
    const float* Wq = (const float*)d_in[1];
    const float* Wk = (const float*)d_in[2];
    const float* Wv = (const float*)d_in[3];
    const float* Wo = (const float*)d_in[4];
    const float* bo = (const float*)d_in[5];
    float* out = (float*)d_out;

    transpose_wo<<<dim3(32, 32), dim3(32, 8)>>>(Wo);

    dim3 g1(DM / 64, NTOK / 64, 3);        // 16 x 128 x 3
    qkv_gemm_kernel<<<g1, 256>>>(x, Wq, Wk, Wv);

    dim3 g2(SEQ / 64, NH, B_);             // 32 x 16 x 4
    flash_kernel<<<g2, 256>>>();

    dim3 g3(DM / 128, NTOK / 128);         // 8 x 64
    out_mma<<<g3, 256>>>(bo, out);
}

// round 10
// speedup vs baseline: 6.3996x; 6.0735x over previous
#include <cuda_runtime.h>
#include <cstdint>

#define B_    4
#define SEQ   2048
#define DM    1024
#define NH    16
#define HD    64
#define NTOK  (B_*SEQ)          // 8192

// ---------------------------------------------------------------------------
// Device scratch (allocation-free rule). NEVER passed as host-side kernel
// args (that was the round-3/6 bug) -- always referenced inside kernels.
// ---------------------------------------------------------------------------
__device__ float g_Q[B_*NH*SEQ*HD];    // [b,h,n,d]
__device__ float g_K[B_*NH*SEQ*HD];    // [b,h,n,d]
__device__ float g_V[B_*NH*SEQ*HD];    // [b,h,n,d]  (kept for safety)
__device__ float g_VT[B_*NH*HD*SEQ];   // [b,h,d,n]  (PV mma B-operand)
__device__ float g_ctx[NTOK*DM];       // [token, D]
__device__ float g_WT[4*DM*DM];        // W^T: [n][k] for q,k,v,o

// ---------------------------------------------------------------------------
__device__ __forceinline__ uint32_t f2tf32(float x) {
    uint32_t u;
    asm("cvt.rna.tf32.f32 %0, %1;" : "=r"(u) : "f"(x));
    return u;
}

__device__ __forceinline__ void mma_tf32(float* d, const uint32_t* a,
                                         uint32_t b0, uint32_t b1) {
    asm volatile(
        "mma.sync.aligned.m16n8k8.row.col.f32.tf32.tf32.f32 "
        "{%0,%1,%2,%3}, {%4,%5,%6,%7}, {%8,%9}, {%0,%1,%2,%3};"
        : "+f"(d[0]), "+f"(d[1]), "+f"(d[2]), "+f"(d[3])
        : "r"(a[0]), "r"(a[1]), "r"(a[2]), "r"(a[3]), "r"(b0), "r"(b1));
}

// 64-col-row swizzled smem addressing (two 32-word halves, quad-XOR swizzle)
__device__ __forceinline__ int SWA(int m, int k) {
    return m * 64 + (k & 32) + (((((k) >> 2) & 7) ^ (m & 7)) << 2) + (k & 3);
}

// ---------------------------------------------------------------------------
// Weight transpose: g_WT[z][n][k] = W_z[k][n]
// ---------------------------------------------------------------------------
__global__ __launch_bounds__(256) void transpose_w(
    const float* __restrict__ Wq, const float* __restrict__ Wk,
    const float* __restrict__ Wv, const float* __restrict__ Wo)
{
    __shared__ float t[32][33];
    const float* src = (blockIdx.z == 0) ? Wq : (blockIdx.z == 1) ? Wk :
                       (blockIdx.z == 2) ? Wv : Wo;
    float* dst = g_WT + (size_t)blockIdx.z * DM * DM;

    int tx = threadIdx.x, ty = threadIdx.y;
    int x0 = blockIdx.x * 32, y0 = blockIdx.y * 32;
    #pragma unroll
    for (int j = ty; j < 32; j += 8)
        t[j][tx] = src[(size_t)(y0 + j) * DM + x0 + tx];
    __syncthreads();
    #pragma unroll
    for (int j = ty; j < 32; j += 8)
        dst[(size_t)(x0 + j) * DM + y0 + tx] = t[tx][j];
}

// ---------------------------------------------------------------------------
// QKV projection via tf32 mma (machinery validated round 7).
// C[128x128] = x[128xK] @ WT_z[128xK]^T, K=1024, BK=32.
// Scatter: z=0 -> g_Q, z=1 -> g_K, z=2 -> g_V + g_VT (transposed).
// ---------------------------------------------------------------------------
__global__ __launch_bounds__(256, 2) void qkv_mma(const float* __restrict__ Agm)
{
    __shared__ __align__(16) uint32_t sA[128 * 32];
    __shared__ __align__(16) uint32_t sB[128 * 32];

    const int tid   = threadIdx.x;
    const int lane  = tid & 31;
    const int wid   = tid >> 5;
    const int warpM = wid & 1;
    const int warpN = wid >> 1;
    const int row0  = blockIdx.y * 128;
    const int col0  = blockIdx.x * 128;
    const int z     = blockIdx.z;
    const float* Bgm = g_WT + (size_t)z * DM * DM;

    const int cm  = tid >> 3;
    const int ckq = tid & 7;
    const int g   = lane >> 2;
    const int t4  = lane & 3;

    float acc[4][4][4] = {};

    for (int c = 0; c < DM / 32; c++) {
        const int kbase = c * 32 + ckq * 4;
        #pragma unroll
        for (int t = 0; t < 4; t++) {
            int m = cm + t * 32;
            float4 va = *(const float4*)&Agm[(size_t)(row0 + m) * DM + kbase];
            float4 vb = *(const float4*)&Bgm[(size_t)(col0 + m) * DM + kbase];
            uint32_t off = (uint32_t)(m * 32 + ((ckq ^ (m & 7)) << 2));
            uint4 ua = { f2tf32(va.x), f2tf32(va.y), f2tf32(va.z), f2tf32(va.w) };
            uint4 ub = { f2tf32(vb.x), f2tf32(vb.y), f2tf32(vb.z), f2tf32(vb.w) };
            *(uint4*)&sA[off] = ua;
            *(uint4*)&sB[off] = ub;
        }
        __syncthreads();

        #pragma unroll
        for (int kb = 0; kb < 4; kb++) {
            const int qlo = ((kb * 2 + 0) ^ g) << 2;
            const int qhi = ((kb * 2 + 1) ^ g) << 2;

            uint32_t a[4][4];
            #pragma unroll
            for (int mf = 0; mf < 4; mf++) {
                int mr = warpM * 64 + mf * 16;
                a[mf][0] = sA[(mr + g)     * 32 + qlo + t4];
                a[mf][1] = sA[(mr + 8 + g) * 32 + qlo + t4];
                a[mf][2] = sA[(mr + g)     * 32 + qhi + t4];
                a[mf][3] = sA[(mr + 8 + g) * 32 + qhi + t4];
            }
            uint32_t b[4][2];
            #pragma unroll
            for (int nf = 0; nf < 4; nf++) {
                int nr = warpN * 32 + nf * 8 + g;
                b[nf][0] = sB[nr * 32 + qlo + t4];
                b[nf][1] = sB[nr * 32 + qhi + t4];
            }
            #pragma unroll
            for (int mf = 0; mf < 4; mf++)
                #pragma unroll
                for (int nf = 0; nf < 4; nf++)
                    mma_tf32(acc[mf][nf], a[mf], b[nf][0], b[nf][1]);
        }
        __syncthreads();
    }

    #pragma unroll
    for (int mf = 0; mf < 4; mf++) {
        #pragma unroll
        for (int half = 0; half < 2; half++) {
            int gr = row0 + warpM * 64 + mf * 16 + g + half * 8;
            int bb = gr >> 11, n = gr & (SEQ - 1);
            #pragma unroll
            for (int nf = 0; nf < 4; nf++) {
                int gc = col0 + warpN * 32 + nf * 8 + t4 * 2;
                int h = gc >> 6, d = gc & 63;
                float v0 = acc[mf][nf][half * 2 + 0];
                float v1 = acc[mf][nf][half * 2 + 1];
                size_t bh = (size_t)(bb * NH + h);
                if (z == 0) {
                    *(float2*)&g_Q[(bh * SEQ + n) * HD + d] = make_float2(v0, v1);
                } else if (z == 1) {
                    *(float2*)&g_K[(bh * SEQ + n) * HD + d] = make_float2(v0, v1);
                } else {
                    *(float2*)&g_V[(bh * SEQ + n) * HD + d] = make_float2(v0, v1);
                    g_VT[(bh * HD + d)     * SEQ + n] = v0;
                    g_VT[(bh * HD + d + 1) * SEQ + n] = v1;
                }
            }
        }
    }
}

// ---------------------------------------------------------------------------
// Flash attention (causal) via tf32 mma. 128 queries/block, 64-key tiles.
// 8 warps x 16 query rows. Fragment mappings identical to validated GEMM.
// ---------------------------------------------------------------------------
__global__ __launch_bounds__(256) void flash_mma()
{
    __shared__ __align__(16) uint32_t sK[64 * 64];    // [key][d] swizzled
    __shared__ __align__(16) uint32_t sVT[64 * 64];   // [d][key] swizzled

    const int tid  = threadIdx.x;
    const int lane = tid & 31;
    const int w    = tid >> 5;        // 0..7
    const int g    = lane >> 2;
    const int t    = lane & 3;

    const int qt = blockIdx.x;        // 0..15 (128-query tiles)
    const int h  = blockIdx.y;
    const int b  = blockIdx.z;
    const int q0 = qt * 128;
    const size_t bh = (size_t)(b * NH + h);

    const float* Qg  = g_Q  + bh * SEQ * HD;
    const float* Kg  = g_K  + bh * SEQ * HD;
    const float* VTg = g_VT + bh * HD * SEQ;

    const int wr    = w * 16;
    const int qrow0 = q0 + wr + g;    // this thread's two query rows
    const int qrow1 = qrow0 + 8;

    // Q fragments, register-resident for the whole kernel
    uint32_t qf[8][4];
    #pragma unroll
    for (int kb = 0; kb < 8; kb++) {
        qf[kb][0] = f2tf32(Qg[(size_t)qrow0 * HD + kb * 8 + t]);
        qf[kb][1] = f2tf32(Qg[(size_t)qrow1 * HD + kb * 8 + t]);
        qf[kb][2] = f2tf32(Qg[(size_t)qrow0 * HD + kb * 8 + t + 4]);
        qf[kb][3] = f2tf32(Qg[(size_t)qrow1 * HD + kb * 8 + t + 4]);
    }

    float o[8][4] = {};
    float m0 = -1e30f, m1 = -1e30f;
    float l0 = 0.f, l1 = 0.f;          // lane-partial row sums

    const int ntiles = 2 * qt + 2;
    for (int kt = 0; kt < ntiles; kt++) {
        const int k0 = kt * 64;

        // ---- stage K tile [64 keys x 64 d] and VT tile [64 d x 64 keys] ----
        {
            const int rr0 = tid >> 4;          // 0..15
            const int cq  = (tid & 15) * 4;    // 0..60
            #pragma unroll
            for (int i = 0; i < 4; i++) {
                int rr = rr0 + i * 16;
                float4 kv = *(const float4*)&Kg[(size_t)(k0 + rr) * HD + cq];
                float4 vv = *(const float4*)&VTg[(size_t)rr * SEQ + k0 + cq];
                uint4 uk = { f2tf32(kv.x), f2tf32(kv.y), f2tf32(kv.z), f2tf32(kv.w) };
                uint4 uv = { f2tf32(vv.x), f2tf32(vv.y), f2tf32(vv.z), f2tf32(vv.w) };
                *(uint4*)&sK[SWA(rr, cq)]  = uk;
                *(uint4*)&sVT[SWA(rr, cq)] = uv;
            }
        }
        __syncthreads();

        // ---- S = Q @ K^T  (warp tile 16 x 64) ----
        float s[8][4] = {};
        #pragma unroll
        for (int kb = 0; kb < 8; kb++) {
            #pragma unroll
            for (int nf = 0; nf < 8; nf++) {
                uint32_t b0 = sK[SWA(nf * 8 + g, kb * 8 + t)];
                uint32_t b1 = sK[SWA(nf * 8 + g, kb * 8 + t + 4)];
                mma_tf32(s[nf], qf[kb], b0, b1);
            }
        }

        // ---- scale + causal mask + row max ----
        float mx0 = -1e30f, mx1 = -1e30f;
        #pragma unroll
        for (int nf = 0; nf < 8; nf++) {
            #pragma unroll
            for (int e = 0; e < 2; e++) {
                int col = k0 + nf * 8 + 2 * t + e;
                float v0 = (col > qrow0) ? -1e30f : s[nf][e] * 0.125f;
                float v1 = (col > qrow1) ? -1e30f : s[nf][2 + e] * 0.125f;
                s[nf][e]     = v0;
                s[nf][2 + e] = v1;
                mx0 = fmaxf(mx0, v0);
                mx1 = fmaxf(mx1, v1);
            }
        }
        mx0 = fmaxf(mx0, __shfl_xor_sync(0xffffffffu, mx0, 1));
        mx0 = fmaxf(mx0, __shfl_xor_sync(0xffffffffu, mx0, 2));
        mx1 = fmaxf(mx1, __shfl_xor_sync(0xffffffffu, mx1, 1));
        mx1 = fmaxf(mx1, __shfl_xor_sync(0xffffffffu, mx1, 2));

        float nm0 = fmaxf(m0, mx0);
        float nm1 = fmaxf(m1, mx1);
        float c0 = __expf(m0 - nm0);
        float c1 = __expf(m1 - nm1);
        m0 = nm0; m1 = nm1;
        l0 *= c0; l1 *= c1;
        #pragma unroll
        for (int nf = 0; nf < 8; nf++) {
            o[nf][0] *= c0; o[nf][1] *= c0;
            o[nf][2] *= c1; o[nf][3] *= c1;
        }

        // ---- p = exp(s - m), lane-partial row sums ----
        #pragma unroll
        for (int nf = 0; nf < 8; nf++) {
            float p0 = __expf(s[nf][0] - m0);
            float p1 = __expf(s[nf][1] - m0);
            float p2 = __expf(s[nf][2] - m1);
            float p3 = __expf(s[nf][3] - m1);
            s[nf][0] = p0; s[nf][1] = p1; s[nf][2] = p2; s[nf][3] = p3;
            l0 += p0 + p1;
            l1 += p2 + p3;
        }

        // ---- PV: redistribute P C-frag -> A-frag via quad shuffles, mma ----
        #pragma unroll
        for (int kb = 0; kb < 8; kb++) {
            const int s0 = (lane & ~3) | (t >> 1);
            const int s1 = s0 + 2;
            float lox0 = __shfl_sync(0xffffffffu, s[kb][0], s0);
            float loy0 = __shfl_sync(0xffffffffu, s[kb][1], s0);
            float hix0 = __shfl_sync(0xffffffffu, s[kb][2], s0);
            float hiy0 = __shfl_sync(0xffffffffu, s[kb][3], s0);
            float lox1 = __shfl_sync(0xffffffffu, s[kb][0], s1);
            float loy1 = __shfl_sync(0xffffffffu, s[kb][1], s1);
            float hix1 = __shfl_sync(0xffffffffu, s[kb][2], s1);
            float hiy1 = __shfl_sync(0xffffffffu, s[kb][3], s1);
            const bool e = (t & 1);
            uint32_t pa[4];
            pa[0] = f2tf32(e ? loy0 : lox0);   // P[g][kb*8+t]
            pa[1] = f2tf32(e ? hiy0 : hix0);   // P[g+8][kb*8+t]
            pa[2] = f2tf32(e ? loy1 : lox1);   // P[g][kb*8+t+4]
            pa[3] = f2tf32(e ? hiy1 : hix1);   // P[g+8][kb*8+t+4]

            #pragma unroll
            for (int nf = 0; nf < 8; nf++) {
                uint32_t b0 = sVT[SWA(nf * 8 + g, kb * 8 + t)];
                uint32_t b1 = sVT[SWA(nf * 8 + g, kb * 8 + t + 4)];
                mma_tf32(o[nf], pa, b0, b1);
            }
        }
        __syncthreads();
    }

    // ---- finalize: quad-reduce l, normalize, write ctx ----
    l0 += __shfl_xor_sync(0xffffffffu, l0, 1);
    l0 += __shfl_xor_sync(0xffffffffu, l0, 2);
    l1 += __shfl_xor_sync(0xffffffffu, l1, 1);
    l1 += __shfl_xor_sync(0xffffffffu, l1, 2);
    const float inv0 = 1.f / l0;
    const float inv1 = 1.f / l1;

    #pragma unroll
    for (int nf = 0; nf < 8; nf++) {
        int dc = h * HD + nf * 8 + 2 * t;
        *(float2*)&g_ctx[(size_t)(b * SEQ + qrow0) * DM + dc]
            = make_float2(o[nf][0] * inv0, o[nf][1] * inv0);
        *(float2*)&g_ctx[(size_t)(b * SEQ + qrow1) * DM + dc]
            = make_float2(o[nf][2] * inv1, o[nf][3] * inv1);
    }
}

// ---------------------------------------------------------------------------
// Out-projection via tf32 mma -- validated round 7, unchanged.
// ---------------------------------------------------------------------------
__global__ __launch_bounds__(256, 2) void out_mma(
    const float* __restrict__ bias,
    float* __restrict__ Cout)
{
    __shared__ __align__(16) uint32_t sA[128 * 32];
    __shared__ __align__(16) uint32_t sB[128 * 32];

    const int tid   = threadIdx.x;
    const int lane  = tid & 31;
    const int wid   = tid >> 5;
    const int warpM = wid & 1;
    const int warpN = wid >> 1;
    const int row0  = blockIdx.y * 128;
    const int col0  = blockIdx.x * 128;
    const float* Bgm = g_WT + (size_t)3 * DM * DM;

    const int cm  = tid >> 3;
    const int ckq = tid & 7;
    const int g   = lane >> 2;
    const int t4  = lane & 3;

    float acc[4][4][4] = {};

    for (int c = 0; c < DM / 32; c++) {
        const int kbase = c * 32 + ckq * 4;
        #pragma unroll
        for (int t = 0; t < 4; t++) {
            int m = cm + t * 32;
            float4 va = *(const float4*)&g_ctx[(size_t)(row0 + m) * DM + kbase];
            float4 vb = *(const float4*)&Bgm[(size_t)(col0 + m) * DM + kbase];
            uint32_t off = (uint32_t)(m * 32 + ((ckq ^ (m & 7)) << 2));
            uint4 ua = { f2tf32(va.x), f2tf32(va.y), f2tf32(va.z), f2tf32(va.w) };
            uint4 ub = { f2tf32(vb.x), f2tf32(vb.y), f2tf32(vb.z), f2tf32(vb.w) };
            *(uint4*)&sA[off] = ua;
            *(uint4*)&sB[off] = ub;
        }
        __syncthreads();

        #pragma unroll
        for (int kb = 0; kb < 4; kb++) {
            const int qlo = ((kb * 2 + 0) ^ g) << 2;
            const int qhi = ((kb * 2 + 1) ^ g) << 2;

            uint32_t a[4][4];
            #pragma unroll
            for (int mf = 0; mf < 4; mf++) {
                int mr = warpM * 64 + mf * 16;
                a[mf][0] = sA[(mr + g)     * 32 + qlo + t4];
                a[mf][1] = sA[(mr + 8 + g) * 32 + qlo + t4];
                a[mf][2] = sA[(mr + g)     * 32 + qhi + t4];
                a[mf][3] = sA[(mr + 8 + g) * 32 + qhi + t4];
            }
            uint32_t b[4][2];
            #pragma unroll
            for (int nf = 0; nf < 4; nf++) {
                int nr = warpN * 32 + nf * 8 + g;
                b[nf][0] = sB[nr * 32 + qlo + t4];
                b[nf][1] = sB[nr * 32 + qhi + t4];
            }
            #pragma unroll
            for (int mf = 0; mf < 4; mf++)
                #pragma unroll
                for (int nf = 0; nf < 4; nf++)
                    mma_tf32(acc[mf][nf], a[mf], b[nf][0], b[nf][1]);
        }
        __syncthreads();
    }

    #pragma unroll
    for (int mf = 0; mf < 4; mf++) {
        #pragma unroll
        for (int half = 0; half < 2; half++) {
            int gr = row0 + warpM * 64 + mf * 16 + g + half * 8;
            #pragma unroll
            for (int nf = 0; nf < 4; nf++) {
                int gc = col0 + warpN * 32 + nf * 8 + t4 * 2;
                float2 bv = *(const float2*)&bias[gc];
                *(float2*)&Cout[(size_t)gr * DM + gc]
                    = make_float2(acc[mf][nf][half * 2 + 0] + bv.x,
                                  acc[mf][nf][half * 2 + 1] + bv.y);
            }
        }
    }
}

// ---------------------------------------------------------------------------
extern "C" void kernel_launch(void* const* d_in, const int* in_sizes, int n_in,
                              void* d_out, int out_size)
{
    const float* x  = (const float*)d_in[0];
    const float* Wq = (const float*)d_in[1];
    const float* Wk = (const float*)d_in[2];
    const float* Wv = (const float*)d_in[3];
    const float* Wo = (const float*)d_in[4];
    const float* bo = (const float*)d_in[5];
    float* out = (float*)d_out;

    dim3 gt(32, 32, 4);
    transpose_w<<<gt, dim3(32, 8)>>>(Wq, Wk, Wv, Wo);

    dim3 g1(DM / 128, NTOK / 128, 3);      // 8 x 64 x 3
    qkv_mma<<<g1, 256>>>(x);

    dim3 g2(SEQ / 128, NH, B_);            // 16 x 16 x 4
    flash_mma<<<g2, 256>>>();

    dim3 g3(DM / 128, NTOK / 128);         // 8 x 64
    out_mma<<<g3, 256>>>(bo, out);
}

// round 12
// speedup vs baseline: 7.1926x; 1.1239x over previous
#include <cuda_runtime.h>
#include <cstdint>

#define B_    4
#define SEQ   2048
#define DM    1024
#define NH    16
#define HD    64
#define NTOK  (B_*SEQ)          // 8192
#define NC    (DM/32)           // 32 k-chunks

// ---------------------------------------------------------------------------
// Device scratch -- referenced ONLY inside kernels (round-3/6 lesson).
// ---------------------------------------------------------------------------
__device__ float g_Q[B_*NH*SEQ*HD];    // [b,h,n,d]
__device__ float g_K[B_*NH*SEQ*HD];    // [b,h,n,d]
__device__ float g_V[B_*NH*SEQ*HD];    // [b,h,n,d]
__device__ float g_ctx[NTOK*DM];       // [token, D]
__device__ float g_WT[4*DM*DM];        // W^T: [n][k] for q,k,v,o

// ---------------------------------------------------------------------------
__device__ __forceinline__ uint32_t smem_u32(const void* p) {
    uint32_t a;
    asm("{ .reg .u64 t; cvta.to.shared.u64 t, %1; cvt.u32.u64 %0, t; }" : "=r"(a) : "l"(p));
    return a;
}

__device__ __forceinline__ uint32_t f2tf32(float x) {
    uint32_t u;
    asm("cvt.rna.tf32.f32 %0, %1;" : "=r"(u) : "f"(x));
    return u;
}
__device__ __forceinline__ uint32_t w2tf32(uint32_t w) {   // raw fp32 bits -> tf32
    uint32_t u;
    asm("cvt.rna.tf32.f32 %0, %1;" : "=r"(u) : "f"(__uint_as_float(w)));
    return u;
}

__device__ __forceinline__ void mma_tf32(float* d, const uint32_t* a,
                                         uint32_t b0, uint32_t b1) {
    asm volatile(
        "mma.sync.aligned.m16n8k8.row.col.f32.tf32.tf32.f32 "
        "{%0,%1,%2,%3}, {%4,%5,%6,%7}, {%8,%9}, {%0,%1,%2,%3};"
        : "+f"(d[0]), "+f"(d[1]), "+f"(d[2]), "+f"(d[3])
        : "r"(a[0]), "r"(a[1]), "r"(a[2]), "r"(a[3]), "r"(b0), "r"(b1));
}

__device__ __forceinline__ void cp16(uint32_t dst, const void* src) {
    asm volatile("cp.async.cg.shared.global [%0], [%1], 16;" :: "r"(dst), "l"(src));
}
#define CP_COMMIT() asm volatile("cp.async.commit_group;")
#define CP_WAIT1()  asm volatile("cp.async.wait_group 1;")

// 64-col-row swizzled smem addressing (two 32-word halves, quad-XOR swizzle)
__device__ __forceinline__ int SWA(int m, int k) {
    return m * 64 + (k & 32) + (((((k) >> 2) & 7) ^ (m & 7)) << 2) + (k & 3);
}

// ---------------------------------------------------------------------------
// Weight transpose: g_WT[z][n][k] = W_z[k][n]
// ---------------------------------------------------------------------------
__global__ __launch_bounds__(256) void transpose_w(
    const float* __restrict__ Wq, const float* __restrict__ Wk,
    const float* __restrict__ Wv, const float* __restrict__ Wo)
{
    __shared__ float t[32][33];
    const float* src = (blockIdx.z == 0) ? Wq : (blockIdx.z == 1) ? Wk :
                       (blockIdx.z == 2) ? Wv : Wo;
    float* dst = g_WT + (size_t)blockIdx.z * DM * DM;

    int tx = threadIdx.x, ty = threadIdx.y;
    int x0 = blockIdx.x * 32, y0 = blockIdx.y * 32;
    #pragma unroll
    for (int j = ty; j < 32; j += 8)
        t[j][tx] = src[(size_t)(y0 + j) * DM + x0 + tx];
    __syncthreads();
    #pragma unroll
    for (int j = ty; j < 32; j += 8)
        dst[(size_t)(x0 + j) * DM + y0 + tx] = t[tx][j];
}

// ---------------------------------------------------------------------------
// TF32 mma GEMM, cp.async 2-stage pipeline. 128x128 tile, BK=32.
// Dynamic smem: stage s A at words s*4096, B at words 8192 + s*4096 (raw fp32
// bits; tf32 conversion applied at fragment-load time).
// MODE 0: C = x @ WT_z^T -> scatter g_Q/g_K/g_V.  MODE 1: C = ctx @ WoT^T + b.
// ---------------------------------------------------------------------------
template<int MODE>
__global__ __launch_bounds__(256, 2) void gemm_mma(
    const float* __restrict__ Agm_,
    const float* __restrict__ bias,
    float* __restrict__ Cout)
{
    extern __shared__ __align__(16) uint32_t dsm[];

    const int tid   = threadIdx.x;
    const int lane  = tid & 31;
    const int wid   = tid >> 5;
    const int warpM = wid & 1;
    const int warpN = wid >> 1;
    const int row0  = blockIdx.y * 128;
    const int col0  = blockIdx.x * 128;
    const int z     = (MODE == 0) ? blockIdx.z : 3;
    const float* Agm = (MODE == 1) ? (const float*)g_ctx : Agm_;
    const float* Bgm = g_WT + (size_t)z * DM * DM;

    const int cm  = tid >> 3;        // copy row base (0..31), +32*t
    const int ckq = tid & 7;         // float4 index within chunk
    const int g   = lane >> 2;
    const int t4  = lane & 3;

    const uint32_t base_u = smem_u32(dsm);

    // issue one chunk's copies into a stage (8 cp.async per thread)
    auto issue = [&](int c, int stage) {
        const int kbase = c * 32 + ckq * 4;
        const uint32_t a_u = base_u + stage * 16384;
        const uint32_t b_u = base_u + 32768 + stage * 16384;
        #pragma unroll
        for (int t = 0; t < 4; t++) {
            int m = cm + t * 32;
            uint32_t off = (uint32_t)(m * 128 + ((ckq ^ (m & 7)) << 4));
            cp16(a_u + off, &Agm[(size_t)(row0 + m) * DM + kbase]);
            cp16(b_u + off, &Bgm[(size_t)(col0 + m) * DM + kbase]);
        }
    };

    float acc[4][4][4] = {};

    issue(0, 0); CP_COMMIT();
    issue(1, 1); CP_COMMIT();

    for (int c = 0; c < NC; c++) {
        CP_WAIT1();
        __syncthreads();

        const uint32_t* A  = dsm + (c & 1) * 4096;
        const uint32_t* Bm = dsm + 8192 + (c & 1) * 4096;

        #pragma unroll
        for (int kb = 0; kb < 4; kb++) {
            const int qlo = ((kb * 2 + 0) ^ g) << 2;
            const int qhi = ((kb * 2 + 1) ^ g) << 2;

            uint32_t a[4][4];
            #pragma unroll
            for (int mf = 0; mf < 4; mf++) {
                int mr = warpM * 64 + mf * 16;
                a[mf][0] = w2tf32(A[(mr + g)     * 32 + qlo + t4]);
                a[mf][1] = w2tf32(A[(mr + 8 + g) * 32 + qlo + t4]);
                a[mf][2] = w2tf32(A[(mr + g)     * 32 + qhi + t4]);
                a[mf][3] = w2tf32(A[(mr + 8 + g) * 32 + qhi + t4]);
            }
            uint32_t b[4][2];
            #pragma unroll
            for (int nf = 0; nf < 4; nf++) {
                int nr = warpN * 32 + nf * 8 + g;
                b[nf][0] = w2tf32(Bm[nr * 32 + qlo + t4]);
                b[nf][1] = w2tf32(Bm[nr * 32 + qhi + t4]);
            }
            #pragma unroll
            for (int mf = 0; mf < 4; mf++)
                #pragma unroll
                for (int nf = 0; nf < 4; nf++)
                    mma_tf32(acc[mf][nf], a[mf], b[nf][0], b[nf][1]);
        }
        __syncthreads();

        if (c + 2 < NC) issue(c + 2, c & 1);
        CP_COMMIT();
    }

    // ---- epilogue ----
    #pragma unroll
    for (int mf = 0; mf < 4; mf++) {
        #pragma unroll
        for (int half = 0; half < 2; half++) {
            int gr = row0 + warpM * 64 + mf * 16 + g + half * 8;
            int bb = gr >> 11, n = gr & (SEQ - 1);
            #pragma unroll
            for (int nf = 0; nf < 4; nf++) {
                int gc = col0 + warpN * 32 + nf * 8 + t4 * 2;
                float v0 = acc[mf][nf][half * 2 + 0];
                float v1 = acc[mf][nf][half * 2 + 1];
                if (MODE == 0) {
                    int h = gc >> 6, d = gc & 63;
                    size_t bh = (size_t)(bb * NH + h);
                    float* outs = (z == 0) ? g_Q : (z == 1) ? g_K : g_V;
                    *(float2*)&outs[(bh * SEQ + n) * HD + d] = make_float2(v0, v1);
                } else {
                    float2 bv = *(const float2*)&bias[gc];
                    *(float2*)&Cout[(size_t)gr * DM + gc]
                        = make_float2(v0 + bv.x, v1 + bv.y);
                }
            }
        }
    }
}

// ---------------------------------------------------------------------------
// Flash attention (causal) via tf32 mma. 128 queries/block, 64-key tiles.
// 8 warps x 16 query rows. PV B-operand read from the [key][d] V tile with
// swapped indices (2-way bank conflicts worst case). Q prescaled by 1/8.
// ---------------------------------------------------------------------------
__global__ __launch_bounds__(256) void flash_mma()
{
    __shared__ __align__(16) uint32_t sK[64 * 64];    // [key][d] swizzled
    __shared__ __align__(16) uint32_t sV[64 * 64];    // [key][d] swizzled

    const int tid  = threadIdx.x;
    const int lane = tid & 31;
    const int w    = tid >> 5;
    const int g    = lane >> 2;
    const int t    = lane & 3;

    const int qt = blockIdx.x;
    const int h  = blockIdx.y;
    const int b  = blockIdx.z;
    const int q0 = qt * 128;
    const size_t bh = (size_t)(b * NH + h);

    const float* Qg = g_Q + bh * SEQ * HD;
    const float* Kg = g_K + bh * SEQ * HD;
    const float* Vg = g_V + bh * SEQ * HD;

    const int qrow0 = q0 + w * 16 + g;
    const int qrow1 = qrow0 + 8;

    // Q fragments, prescaled by 1/sqrt(64) = 0.125
    uint32_t qf[8][4];
    #pragma unroll
    for (int kb = 0; kb < 8; kb++) {
        qf[kb][0] = f2tf32(0.125f * Qg[(size_t)qrow0 * HD + kb * 8 + t]);
        qf[kb][1] = f2tf32(0.125f * Qg[(size_t)qrow1 * HD + kb * 8 + t]);
        qf[kb][2] = f2tf32(0.125f * Qg[(size_t)qrow0 * HD + kb * 8 + t + 4]);
        qf[kb][3] = f2tf32(0.125f * Qg[(size_t)qrow1 * HD + kb * 8 + t + 4]);
    }

    float o[8][4] = {};
    float m0 = -1e30f, m1 = -1e30f;
    float l0 = 0.f, l1 = 0.f;

    const int ntiles = 2 * qt + 2;
    for (int kt = 0; kt < ntiles; kt++) {
        const int k0 = kt * 64;

        // ---- stage K and V tiles (both [64 keys][64 d], coalesced) ----
        {
            const int rr0 = tid >> 4;
            const int cq  = (tid & 15) * 4;
            #pragma unroll
            for (int i = 0; i < 4; i++) {
                int rr = rr0 + i * 16;
                float4 kv = *(const float4*)&Kg[(size_t)(k0 + rr) * HD + cq];
                float4 vv = *(const float4*)&Vg[(size_t)(k0 + rr) * HD + cq];
                uint4 uk = { f2tf32(kv.x), f2tf32(kv.y), f2tf32(kv.z), f2tf32(kv.w) };
                uint4 uv = { f2tf32(vv.x), f2tf32(vv.y), f2tf32(vv.z), f2tf32(vv.w) };
                *(uint4*)&sK[SWA(rr, cq)] = uk;
                *(uint4*)&sV[SWA(rr, cq)] = uv;
            }
        }
        __syncthreads();

        // ---- S = Q @ K^T ----
        float s[8][4] = {};
        #pragma unroll
        for (int kb = 0; kb < 8; kb++) {
            #pragma unroll
            for (int nf = 0; nf < 8; nf++) {
                uint32_t b0 = sK[SWA(nf * 8 + g, kb * 8 + t)];
                uint32_t b1 = sK[SWA(nf * 8 + g, kb * 8 + t + 4)];
                mma_tf32(s[nf], qf[kb], b0, b1);
            }
        }

        // ---- causal mask (only near diagonal) + row max ----
        float mx0 = -1e30f, mx1 = -1e30f;
        if (k0 + 63 > qrow0) {
            #pragma unroll
            for (int nf = 0; nf < 8; nf++) {
                #pragma unroll
                for (int e = 0; e < 2; e++) {
                    int col = k0 + nf * 8 + 2 * t + e;
                    if (col > qrow0) s[nf][e]     = -1e30f;
                    if (col > qrow1) s[nf][2 + e] = -1e30f;
                    mx0 = fmaxf(mx0, s[nf][e]);
                    mx1 = fmaxf(mx1, s[nf][2 + e]);
                }
            }
        } else {
            #pragma unroll
            for (int nf = 0; nf < 8; nf++) {
                mx0 = fmaxf(mx0, fmaxf(s[nf][0], s[nf][1]));
                mx1 = fmaxf(mx1, fmaxf(s[nf][2], s[nf][3]));
            }
        }
        mx0 = fmaxf(mx0, __shfl_xor_sync(0xffffffffu, mx0, 1));
        mx0 = fmaxf(mx0, __shfl_xor_sync(0xffffffffu, mx0, 2));
        mx1 = fmaxf(mx1, __shfl_xor_sync(0xffffffffu, mx1, 1));
        mx1 = fmaxf(mx1, __shfl_xor_sync(0xffffffffu, mx1, 2));

        float nm0 = fmaxf(m0, mx0);
        float nm1 = fmaxf(m1, mx1);
        float c0 = __expf(m0 - nm0);
        float c1 = __expf(m1 - nm1);
        m0 = nm0; m1 = nm1;
        l0 *= c0; l1 *= c1;
        #pragma unroll
        for (int nf = 0; nf < 8; nf++) {
            o[nf][0] *= c0; o[nf][1] *= c0;
            o[nf][2] *= c1; o[nf][3] *= c1;
        }

        // ---- p = exp(s - m), lane-partial row sums ----
        #pragma unroll
        for (int nf = 0; nf < 8; nf++) {
            float p0 = __expf(s[nf][0] - m0);
            float p1 = __expf(s[nf][1] - m0);
            float p2 = __expf(s[nf][2] - m1);
            float p3 = __expf(s[nf][3] - m1);
            s[nf][0] = p0; s[nf][1] = p1; s[nf][2] = p2; s[nf][3] = p3;
            l0 += p0 + p1;
            l1 += p2 + p3;
        }

        // ---- PV: P C-frag -> A-frag via quad shuffles; B from sV swapped ----
        #pragma unroll
        for (int kb = 0; kb < 8; kb++) {
            const int s0 = (lane & ~3) | (t >> 1);
            const int s1 = s0 + 2;
            float lox0 = __shfl_sync(0xffffffffu, s[kb][0], s0);
            float loy0 = __shfl_sync(0xffffffffu, s[kb][1], s0);
            float hix0 = __shfl_sync(0xffffffffu, s[kb][2], s0);
            float hiy0 = __shfl_sync(0xffffffffu, s[kb][3], s0);
            float lox1 = __shfl_sync(0xffffffffu, s[kb][0], s1);
            float loy1 = __shfl_sync(0xffffffffu, s[kb][1], s1);
            float hix1 = __shfl_sync(0xffffffffu, s[kb][2], s1);
            float hiy1 = __shfl_sync(0xffffffffu, s[kb][3], s1);
            const bool e = (t & 1);
            uint32_t pa[4];
            pa[0] = f2tf32(e ? loy0 : lox0);
            pa[1] = f2tf32(e ? hiy0 : hix0);
            pa[2] = f2tf32(e ? loy1 : lox1);
            pa[3] = f2tf32(e ? hiy1 : hix1);

            #pragma unroll
            for (int nf = 0; nf < 8; nf++) {
                uint32_t b0 = sV[SWA(kb * 8 + t,     nf * 8 + g)];
                uint32_t b1 = sV[SWA(kb * 8 + t + 4, nf * 8 + g)];
                mma_tf32(o[nf], pa, b0, b1);
            }
        }
        __syncthreads();
    }

    // ---- finalize ----
    l0 += __shfl_xor_sync(0xffffffffu, l0, 1);
    l0 += __shfl_xor_sync(0xffffffffu, l0, 2);
    l1 += __shfl_xor_sync(0xffffffffu, l1, 1);
    l1 += __shfl_xor_sync(0xffffffffu, l1, 2);
    const float inv0 = 1.f / l0;
    const float inv1 = 1.f / l1;

    #pragma unroll
    for (int nf = 0; nf < 8; nf++) {
        int dc = h * HD + nf * 8 + 2 * t;
        *(float2*)&g_ctx[(size_t)(b * SEQ + qrow0) * DM + dc]
            = make_float2(o[nf][0] * inv0, o[nf][1] * inv0);
        *(float2*)&g_ctx[(size_t)(b * SEQ + qrow1) * DM + dc]
            = make_float2(o[nf][2] * inv1, o[nf][3] * inv1);
    }
}

// ---------------------------------------------------------------------------
extern "C" void kernel_launch(void* const* d_in, const int* in_sizes, int n_in,
                              void* d_out, int out_size)
{
    const float* x  = (const float*)d_in[0];
    const float* Wq = (const float*)d_in[1];
    const float* Wk = (const float*)d_in[2];
    const float* Wv = (const float*)d_in[3];
    const float* Wo = (const float*)d_in[4];
    const float* bo = (const float*)d_in[5];
    float* out = (float*)d_out;

    cudaFuncSetAttribute(gemm_mma<0>, cudaFuncAttributeMaxDynamicSharedMemorySize, 65536);
    cudaFuncSetAttribute(gemm_mma<1>, cudaFuncAttributeMaxDynamicSharedMemorySize, 65536);

    dim3 gt(32, 32, 4);
    transpose_w<<<gt, dim3(32, 8)>>>(Wq, Wk, Wv, Wo);

    dim3 g1(DM / 128, NTOK / 128, 3);      // 8 x 64 x 3
    gemm_mma<0><<<g1, 256, 65536>>>(x, nullptr, nullptr);

    dim3 g2(SEQ / 128, NH, B_);            // 16 x 16 x 4
    flash_mma<<<g2, 256>>>();

    dim3 g3(DM / 128, NTOK / 128);         // 8 x 64
    gemm_mma<1><<<g3, 256, 65536>>>(nullptr, bo, out);
}

// round 13
// speedup vs baseline: 7.9997x; 1.1122x over previous
#include <cuda_runtime.h>
#include <cstdint>

#define B_    4
#define SEQ   2048
#define DM    1024
#define NH    16
#define HD    64
#define NTOK  (B_*SEQ)          // 8192
#define NC    (DM/32)           // 32 k-chunks

// ---------------------------------------------------------------------------
// Device scratch -- referenced ONLY inside kernels (round-3/6 lesson).
// All of these hold tf32-pre-rounded values (stored as float bit patterns),
// except g_ctx consumers see tf32-rounded too. Rounding at producer makes
// every mma operand path a raw load (mma tf32 truncation is then lossless).
// ---------------------------------------------------------------------------
__device__ float g_xc[NTOK*DM];        // x pre-rounded to tf32
__device__ float g_Q[B_*NH*SEQ*HD];    // [b,h,n,d] tf32-rounded
__device__ float g_K[B_*NH*SEQ*HD];    // [b,h,n,d] tf32-rounded
__device__ float g_V[B_*NH*SEQ*HD];    // [b,h,n,d] tf32-rounded
__device__ float g_ctx[NTOK*DM];       // [token, D] tf32-rounded
__device__ float g_WT[4*DM*DM];        // W^T: [n][k], tf32-rounded

// ---------------------------------------------------------------------------
__device__ __forceinline__ uint32_t smem_u32(const void* p) {
    uint32_t a;
    asm("{ .reg .u64 t; cvta.to.shared.u64 t, %1; cvt.u32.u64 %0, t; }" : "=r"(a) : "l"(p));
    return a;
}

__device__ __forceinline__ uint32_t f2tf32(float x) {
    uint32_t u;
    asm("cvt.rna.tf32.f32 %0, %1;" : "=r"(u) : "f"(x));
    return u;
}
__device__ __forceinline__ float rnd_tf32(float x) {
    return __uint_as_float(f2tf32(x));
}

__device__ __forceinline__ void mma_tf32(float* d, const uint32_t* a,
                                         uint32_t b0, uint32_t b1) {
    asm volatile(
        "mma.sync.aligned.m16n8k8.row.col.f32.tf32.tf32.f32 "
        "{%0,%1,%2,%3}, {%4,%5,%6,%7}, {%8,%9}, {%0,%1,%2,%3};"
        : "+f"(d[0]), "+f"(d[1]), "+f"(d[2]), "+f"(d[3])
        : "r"(a[0]), "r"(a[1]), "r"(a[2]), "r"(a[3]), "r"(b0), "r"(b1));
}

__device__ __forceinline__ void cp16(uint32_t dst, const void* src) {
    asm volatile("cp.async.cg.shared.global [%0], [%1], 16;" :: "r"(dst), "l"(src));
}
#define CP_COMMIT() asm volatile("cp.async.commit_group;")
#define CP_WAIT1()  asm volatile("cp.async.wait_group 1;")

// 64-col-row swizzled smem addressing (two 32-word halves, quad-XOR swizzle)
__device__ __forceinline__ int SWA(int m, int k) {
    return m * 64 + (k & 32) + (((((k) >> 2) & 7) ^ (m & 7)) << 2) + (k & 3);
}

// ---------------------------------------------------------------------------
// x pre-round to tf32: g_xc = rna_tf32(x)
// ---------------------------------------------------------------------------
__global__ __launch_bounds__(256) void cvt_x(const float* __restrict__ x)
{
    const int i0 = (blockIdx.x * 256 + threadIdx.x) * 4;
    const int stride = gridDim.x * 256 * 4;
    for (int i = i0; i < NTOK * DM; i += stride) {
        float4 v = *(const float4*)&x[i];
        v.x = rnd_tf32(v.x); v.y = rnd_tf32(v.y);
        v.z = rnd_tf32(v.z); v.w = rnd_tf32(v.w);
        *(float4*)&g_xc[i] = v;
    }
}

// ---------------------------------------------------------------------------
// Weight transpose + tf32 round: g_WT[z][n][k] = rna_tf32(W_z[k][n])
// ---------------------------------------------------------------------------
__global__ __launch_bounds__(256) void transpose_w(
    const float* __restrict__ Wq, const float* __restrict__ Wk,
    const float* __restrict__ Wv, const float* __restrict__ Wo)
{
    __shared__ float t[32][33];
    const float* src = (blockIdx.z == 0) ? Wq : (blockIdx.z == 1) ? Wk :
                       (blockIdx.z == 2) ? Wv : Wo;
    float* dst = g_WT + (size_t)blockIdx.z * DM * DM;

    int tx = threadIdx.x, ty = threadIdx.y;
    int x0 = blockIdx.x * 32, y0 = blockIdx.y * 32;
    #pragma unroll
    for (int j = ty; j < 32; j += 8)
        t[j][tx] = src[(size_t)(y0 + j) * DM + x0 + tx];
    __syncthreads();
    #pragma unroll
    for (int j = ty; j < 32; j += 8)
        dst[(size_t)(x0 + j) * DM + y0 + tx] = rnd_tf32(t[tx][j]);
}

// ---------------------------------------------------------------------------
// TF32 mma GEMM, cp.async 2-stage pipeline, raw tf32-bit operands (no cvt).
// MODE 0: C = xc @ WT_z^T -> scatter g_Q/g_K/g_V (tf32-rounded at write).
// MODE 1: C = ctx @ WoT^T + bias -> out (full fp32).
// ---------------------------------------------------------------------------
template<int MODE>
__global__ __launch_bounds__(256, 2) void gemm_mma(
    const float* __restrict__ bias,
    float* __restrict__ Cout)
{
    extern __shared__ __align__(16) uint32_t dsm[];

    const int tid   = threadIdx.x;
    const int lane  = tid & 31;
    const int wid   = tid >> 5;
    const int warpM = wid & 1;
    const int warpN = wid >> 1;
    const int row0  = blockIdx.y * 128;
    const int col0  = blockIdx.x * 128;
    const int z     = (MODE == 0) ? blockIdx.z : 3;
    const float* Agm = (MODE == 0) ? (const float*)g_xc : (const float*)g_ctx;
    const float* Bgm = g_WT + (size_t)z * DM * DM;

    const int cm  = tid >> 3;
    const int ckq = tid & 7;
    const int g   = lane >> 2;
    const int t4  = lane & 3;

    const uint32_t base_u = smem_u32(dsm);

    auto issue = [&](int c, int stage) {
        const int kbase = c * 32 + ckq * 4;
        const uint32_t a_u = base_u + stage * 16384;
        const uint32_t b_u = base_u + 32768 + stage * 16384;
        #pragma unroll
        for (int t = 0; t < 4; t++) {
            int m = cm + t * 32;
            uint32_t off = (uint32_t)(m * 128 + ((ckq ^ (m & 7)) << 4));
            cp16(a_u + off, &Agm[(size_t)(row0 + m) * DM + kbase]);
            cp16(b_u + off, &Bgm[(size_t)(col0 + m) * DM + kbase]);
        }
    };

    float acc[4][4][4] = {};

    issue(0, 0); CP_COMMIT();
    issue(1, 1); CP_COMMIT();

    for (int c = 0; c < NC; c++) {
        CP_WAIT1();
        __syncthreads();

        const uint32_t* A  = dsm + (c & 1) * 4096;
        const uint32_t* Bm = dsm + 8192 + (c & 1) * 4096;

        #pragma unroll
        for (int kb = 0; kb < 4; kb++) {
            const int qlo = ((kb * 2 + 0) ^ g) << 2;
            const int qhi = ((kb * 2 + 1) ^ g) << 2;

            uint32_t a[4][4];
            #pragma unroll
            for (int mf = 0; mf < 4; mf++) {
                int mr = warpM * 64 + mf * 16;
                a[mf][0] = A[(mr + g)     * 32 + qlo + t4];
                a[mf][1] = A[(mr + 8 + g) * 32 + qlo + t4];
                a[mf][2] = A[(mr + g)     * 32 + qhi + t4];
                a[mf][3] = A[(mr + 8 + g) * 32 + qhi + t4];
            }
            uint32_t b[4][2];
            #pragma unroll
            for (int nf = 0; nf < 4; nf++) {
                int nr = warpN * 32 + nf * 8 + g;
                b[nf][0] = Bm[nr * 32 + qlo + t4];
                b[nf][1] = Bm[nr * 32 + qhi + t4];
            }
            #pragma unroll
            for (int mf = 0; mf < 4; mf++)
                #pragma unroll
                for (int nf = 0; nf < 4; nf++)
                    mma_tf32(acc[mf][nf], a[mf], b[nf][0], b[nf][1]);
        }
        __syncthreads();

        if (c + 2 < NC) issue(c + 2, c & 1);
        CP_COMMIT();
    }

    // ---- epilogue ----
    #pragma unroll
    for (int mf = 0; mf < 4; mf++) {
        #pragma unroll
        for (int half = 0; half < 2; half++) {
            int gr = row0 + warpM * 64 + mf * 16 + g + half * 8;
            int bb = gr >> 11, n = gr & (SEQ - 1);
            #pragma unroll
            for (int nf = 0; nf < 4; nf++) {
                int gc = col0 + warpN * 32 + nf * 8 + t4 * 2;
                float v0 = acc[mf][nf][half * 2 + 0];
                float v1 = acc[mf][nf][half * 2 + 1];
                if (MODE == 0) {
                    int h = gc >> 6, d = gc & 63;
                    size_t bh = (size_t)(bb * NH + h);
                    float* outs = (z == 0) ? g_Q : (z == 1) ? g_K : g_V;
                    *(float2*)&outs[(bh * SEQ + n) * HD + d]
                        = make_float2(rnd_tf32(v0), rnd_tf32(v1));
                } else {
                    float2 bv = *(const float2*)&bias[gc];
                    *(float2*)&Cout[(size_t)gr * DM + gc]
                        = make_float2(v0 + bv.x, v1 + bv.y);
                }
            }
        }
    }
}

// ---------------------------------------------------------------------------
// Flash attention (causal) via tf32 mma. 128 queries/block, 64-key tiles,
// cp.async 2-stage double-buffered K/V staging (raw: operands pre-rounded).
// 8 warps x 16 query rows. PV B-operand from [key][d] V tile, swapped idx.
// Dynamic smem: stage s: K at words s*8192, V at s*8192+4096 (64 KB total).
// ---------------------------------------------------------------------------
__global__ __launch_bounds__(256) void flash_mma()
{
    extern __shared__ __align__(16) uint32_t fsm[];

    const int tid  = threadIdx.x;
    const int lane = tid & 31;
    const int w    = tid >> 5;
    const int g    = lane >> 2;
    const int t    = lane & 3;

    const int qt = blockIdx.x;
    const int h  = blockIdx.y;
    const int b  = blockIdx.z;
    const int q0 = qt * 128;
    const size_t bh = (size_t)(b * NH + h);

    const float* Qg = g_Q + bh * SEQ * HD;
    const float* Kg = g_K + bh * SEQ * HD;
    const float* Vg = g_V + bh * SEQ * HD;

    const int qrow0 = q0 + w * 16 + g;
    const int qrow1 = qrow0 + 8;

    const uint32_t base_u = smem_u32(fsm);

    auto issue_tile = [&](int kt, int stage) {
        const int k0  = kt * 64;
        const int rr0 = tid >> 4;
        const int cq  = (tid & 15) * 4;
        const uint32_t k_u = base_u + stage * 32768;
        const uint32_t v_u = k_u + 16384;
        #pragma unroll
        for (int i = 0; i < 4; i++) {
            int rr = rr0 + i * 16;
            uint32_t off = (uint32_t)SWA(rr, cq) * 4;
            cp16(k_u + off, &Kg[(size_t)(k0 + rr) * HD + cq]);
            cp16(v_u + off, &Vg[(size_t)(k0 + rr) * HD + cq]);
        }
    };

    // Q fragments: prescale by 0.125 (exact power of two; stays tf32)
    uint32_t qf[8][4];
    #pragma unroll
    for (int kb = 0; kb < 8; kb++) {
        qf[kb][0] = __float_as_uint(0.125f * Qg[(size_t)qrow0 * HD + kb * 8 + t]);
        qf[kb][1] = __float_as_uint(0.125f * Qg[(size_t)qrow1 * HD + kb * 8 + t]);
        qf[kb][2] = __float_as_uint(0.125f * Qg[(size_t)qrow0 * HD + kb * 8 + t + 4]);
        qf[kb][3] = __float_as_uint(0.125f * Qg[(size_t)qrow1 * HD + kb * 8 + t + 4]);
    }

    float o[8][4] = {};
    float m0 = -1e30f, m1 = -1e30f;
    float l0 = 0.f, l1 = 0.f;

    const int ntiles = 2 * qt + 2;     // always >= 2

    issue_tile(0, 0); CP_COMMIT();
    issue_tile(1, 1); CP_COMMIT();

    for (int kt = 0; kt < ntiles; kt++) {
        const int k0 = kt * 64;
        CP_WAIT1();
        __syncthreads();

        const uint32_t* sK = fsm + (kt & 1) * 8192;
        const uint32_t* sV = sK + 4096;

        // ---- S = Q @ K^T ----
        float s[8][4] = {};
        #pragma unroll
        for (int kb = 0; kb < 8; kb++) {
            #pragma unroll
            for (int nf = 0; nf < 8; nf++) {
                uint32_t b0 = sK[SWA(nf * 8 + g, kb * 8 + t)];
                uint32_t b1 = sK[SWA(nf * 8 + g, kb * 8 + t + 4)];
                mma_tf32(s[nf], qf[kb], b0, b1);
            }
        }

        // ---- causal mask (only near diagonal) + row max ----
        float mx0 = -1e30f, mx1 = -1e30f;
        if (k0 + 63 > qrow0) {
            #pragma unroll
            for (int nf = 0; nf < 8; nf++) {
                #pragma unroll
                for (int e = 0; e < 2; e++) {
                    int col = k0 + nf * 8 + 2 * t + e;
                    if (col > qrow0) s[nf][e]     = -1e30f;
                    if (col > qrow1) s[nf][2 + e] = -1e30f;
                    mx0 = fmaxf(mx0, s[nf][e]);
                    mx1 = fmaxf(mx1, s[nf][2 + e]);
                }
            }
        } else {
            #pragma unroll
            for (int nf = 0; nf < 8; nf++) {
                mx0 = fmaxf(mx0, fmaxf(s[nf][0], s[nf][1]));
                mx1 = fmaxf(mx1, fmaxf(s[nf][2], s[nf][3]));
            }
        }
        mx0 = fmaxf(mx0, __shfl_xor_sync(0xffffffffu, mx0, 1));
        mx0 = fmaxf(mx0, __shfl_xor_sync(0xffffffffu, mx0, 2));
        mx1 = fmaxf(mx1, __shfl_xor_sync(0xffffffffu, mx1, 1));
        mx1 = fmaxf(mx1, __shfl_xor_sync(0xffffffffu, mx1, 2));

        float nm0 = fmaxf(m0, mx0);
        float nm1 = fmaxf(m1, mx1);
        float c0 = __expf(m0 - nm0);
        float c1 = __expf(m1 - nm1);
        m0 = nm0; m1 = nm1;
        l0 *= c0; l1 *= c1;
        #pragma unroll
        for (int nf = 0; nf < 8; nf++) {
            o[nf][0] *= c0; o[nf][1] *= c0;
            o[nf][2] *= c1; o[nf][3] *= c1;
        }

        // ---- p = exp(s - m), lane-partial row sums ----
        #pragma unroll
        for (int nf = 0; nf < 8; nf++) {
            float p0 = __expf(s[nf][0] - m0);
            float p1 = __expf(s[nf][1] - m0);
            float p2 = __expf(s[nf][2] - m1);
            float p3 = __expf(s[nf][3] - m1);
            s[nf][0] = p0; s[nf][1] = p1; s[nf][2] = p2; s[nf][3] = p3;
            l0 += p0 + p1;
            l1 += p2 + p3;
        }

        // ---- PV: P C-frag -> A-frag via quad shuffles; B from sV swapped ----
        #pragma unroll
        for (int kb = 0; kb < 8; kb++) {
            const int s0 = (lane & ~3) | (t >> 1);
            const int s1 = s0 + 2;
            float lox0 = __shfl_sync(0xffffffffu, s[kb][0], s0);
            float loy0 = __shfl_sync(0xffffffffu, s[kb][1], s0);
            float hix0 = __shfl_sync(0xffffffffu, s[kb][2], s0);
            float hiy0 = __shfl_sync(0xffffffffu, s[kb][3], s0);
            float lox1 = __shfl_sync(0xffffffffu, s[kb][0], s1);
            float loy1 = __shfl_sync(0xffffffffu, s[kb][1], s1);
            float hix1 = __shfl_sync(0xffffffffu, s[kb][2], s1);
            float hiy1 = __shfl_sync(0xffffffffu, s[kb][3], s1);
            const bool e = (t & 1);
            uint32_t pa[4];
            pa[0] = f2tf32(e ? loy0 : lox0);
            pa[1] = f2tf32(e ? hiy0 : hix0);
            pa[2] = f2tf32(e ? loy1 : lox1);
            pa[3] = f2tf32(e ? hiy1 : hix1);

            #pragma unroll
            for (int nf = 0; nf < 8; nf++) {
                uint32_t b0 = sV[SWA(kb * 8 + t,     nf * 8 + g)];
                uint32_t b1 = sV[SWA(kb * 8 + t + 4, nf * 8 + g)];
                mma_tf32(o[nf], pa, b0, b1);
            }
        }
        __syncthreads();

        if (kt + 2 < ntiles) issue_tile(kt + 2, kt & 1);
        CP_COMMIT();
    }

    // ---- finalize (ctx written tf32-rounded for raw out_mma reads) ----
    l0 += __shfl_xor_sync(0xffffffffu, l0, 1);
    l0 += __shfl_xor_sync(0xffffffffu, l0, 2);
    l1 += __shfl_xor_sync(0xffffffffu, l1, 1);
    l1 += __shfl_xor_sync(0xffffffffu, l1, 2);
    const float inv0 = 1.f / l0;
    const float inv1 = 1.f / l1;

    #pragma unroll
    for (int nf = 0; nf < 8; nf++) {
        int dc = h * HD + nf * 8 + 2 * t;
        *(float2*)&g_ctx[(size_t)(b * SEQ + qrow0) * DM + dc]
            = make_float2(rnd_tf32(o[nf][0] * inv0), rnd_tf32(o[nf][1] * inv0));
        *(float2*)&g_ctx[(size_t)(b * SEQ + qrow1) * DM + dc]
            = make_float2(rnd_tf32(o[nf][2] * inv1), rnd_tf32(o[nf][3] * inv1));
    }
}

// ---------------------------------------------------------------------------
extern "C" void kernel_launch(void* const* d_in, const int* in_sizes, int n_in,
                              void* d_out, int out_size)
{
    const float* x  = (const float*)d_in[0];
    const float* Wq = (const float*)d_in[1];
    const float* Wk = (const float*)d_in[2];
    const float* Wv = (const float*)d_in[3];
    const float* Wo = (const float*)d_in[4];
    const float* bo = (const float*)d_in[5];
    float* out = (float*)d_out;

    cudaFuncSetAttribute(gemm_mma<0>, cudaFuncAttributeMaxDynamicSharedMemorySize, 65536);
    cudaFuncSetAttribute(gemm_mma<1>, cudaFuncAttributeMaxDynamicSharedMemorySize, 65536);
    cudaFuncSetAttribute(flash_mma,   cudaFuncAttributeMaxDynamicSharedMemorySize, 65536);

    cvt_x<<<2048, 256>>>(x);

    dim3 gt(32, 32, 4);
    transpose_w<<<gt, dim3(32, 8)>>>(Wq, Wk, Wv, Wo);

    dim3 g1(DM / 128, NTOK / 128, 3);      // 8 x 64 x 3
    gemm_mma<0><<<g1, 256, 65536>>>(nullptr, nullptr);

    dim3 g2(SEQ / 128, NH, B_);            // 16 x 16 x 4
    flash_mma<<<g2, 256, 65536>>>();

    dim3 g3(DM / 128, NTOK / 128);         // 8 x 64
    gemm_mma<1><<<g3, 256, 65536>>>(bo, out);
}

// round 14
// speedup vs baseline: 8.5085x; 1.0636x over previous
#include <cuda_runtime.h>
#include <cstdint>

#define B_    4
#define SEQ   2048
#define DM    1024
#define NH    16
#define HD    64
#define NTOK  (B_*SEQ)          // 8192
#define NC    (DM/32)           // 32 k-chunks

// ---------------------------------------------------------------------------
// Device scratch -- referenced ONLY inside kernels (round-3/6 lesson).
// All tf32-pre-rounded (rounding at producer makes every mma operand path a
// raw load; mma tf32 truncation is then lossless).
// ---------------------------------------------------------------------------
__device__ float g_xc[NTOK*DM];        // x pre-rounded to tf32
__device__ float g_Q[B_*NH*SEQ*HD];    // [b,h,n,d] tf32-rounded
__device__ float g_K[B_*NH*SEQ*HD];    // [b,h,n,d] tf32-rounded
__device__ float g_V[B_*NH*SEQ*HD];    // [b,h,n,d] tf32-rounded
__device__ float g_ctx[NTOK*DM];       // [token, D] tf32-rounded
__device__ float g_WT[4*DM*DM];        // W^T: [n][k], tf32-rounded

// ---------------------------------------------------------------------------
__device__ __forceinline__ uint32_t smem_u32(const void* p) {
    uint32_t a;
    asm("{ .reg .u64 t; cvta.to.shared.u64 t, %1; cvt.u32.u64 %0, t; }" : "=r"(a) : "l"(p));
    return a;
}

__device__ __forceinline__ uint32_t f2tf32(float x) {
    uint32_t u;
    asm("cvt.rna.tf32.f32 %0, %1;" : "=r"(u) : "f"(x));
    return u;
}
__device__ __forceinline__ float rnd_tf32(float x) {
    return __uint_as_float(f2tf32(x));
}

__device__ __forceinline__ void mma_tf32(float* d, const uint32_t* a,
                                         uint32_t b0, uint32_t b1) {
    asm volatile(
        "mma.sync.aligned.m16n8k8.row.col.f32.tf32.tf32.f32 "
        "{%0,%1,%2,%3}, {%4,%5,%6,%7}, {%8,%9}, {%0,%1,%2,%3};"
        : "+f"(d[0]), "+f"(d[1]), "+f"(d[2]), "+f"(d[3])
        : "r"(a[0]), "r"(a[1]), "r"(a[2]), "r"(a[3]), "r"(b0), "r"(b1));
}

__device__ __forceinline__ void cp16(uint32_t dst, const void* src) {
    asm volatile("cp.async.cg.shared.global [%0], [%1], 16;" :: "r"(dst), "l"(src));
}
#define CP_COMMIT() asm volatile("cp.async.commit_group;")
#define CP_WAIT1()  asm volatile("cp.async.wait_group 1;")

// 64-col-row swizzled smem addressing (two 32-word halves, quad-XOR swizzle)
__device__ __forceinline__ int SWA(int m, int k) {
    return m * 64 + (k & 32) + (((((k) >> 2) & 7) ^ (m & 7)) << 2) + (k & 3);
}

// ---------------------------------------------------------------------------
// x pre-round to tf32: g_xc = rna_tf32(x)
// ---------------------------------------------------------------------------
__global__ __launch_bounds__(256) void cvt_x(const float* __restrict__ x)
{
    const int i0 = (blockIdx.x * 256 + threadIdx.x) * 4;
    const int stride = gridDim.x * 256 * 4;
    for (int i = i0; i < NTOK * DM; i += stride) {
        float4 v = *(const float4*)&x[i];
        v.x = rnd_tf32(v.x); v.y = rnd_tf32(v.y);
        v.z = rnd_tf32(v.z); v.w = rnd_tf32(v.w);
        *(float4*)&g_xc[i] = v;
    }
}

// ---------------------------------------------------------------------------
// Weight transpose + tf32 round: g_WT[z][n][k] = rna_tf32(W_z[k][n])
// ---------------------------------------------------------------------------
__global__ __launch_bounds__(256) void transpose_w(
    const float* __restrict__ Wq, const float* __restrict__ Wk,
    const float* __restrict__ Wv, const float* __restrict__ Wo)
{
    __shared__ float t[32][33];
    const float* src = (blockIdx.z == 0) ? Wq : (blockIdx.z == 1) ? Wk :
                       (blockIdx.z == 2) ? Wv : Wo;
    float* dst = g_WT + (size_t)blockIdx.z * DM * DM;

    int tx = threadIdx.x, ty = threadIdx.y;
    int x0 = blockIdx.x * 32, y0 = blockIdx.y * 32;
    #pragma unroll
    for (int j = ty; j < 32; j += 8)
        t[j][tx] = src[(size_t)(y0 + j) * DM + x0 + tx];
    __syncthreads();
    #pragma unroll
    for (int j = ty; j < 32; j += 8)
        dst[(size_t)(x0 + j) * DM + y0 + tx] = rnd_tf32(t[tx][j]);
}

// ---------------------------------------------------------------------------
// TF32 mma GEMM, cp.async 2-stage pipeline, raw tf32-bit operands (no cvt).
// MODE 0: C = xc @ WT_z^T -> scatter g_Q/g_K/g_V (tf32-rounded at write).
// MODE 1: C = ctx @ WoT^T + bias -> out (full fp32).
// ---------------------------------------------------------------------------
template<int MODE>
__global__ __launch_bounds__(256, 2) void gemm_mma(
    const float* __restrict__ bias,
    float* __restrict__ Cout)
{
    extern __shared__ __align__(16) uint32_t dsm[];

    const int tid   = threadIdx.x;
    const int lane  = tid & 31;
    const int wid   = tid >> 5;
    const int warpM = wid & 1;
    const int warpN = wid >> 1;
    const int row0  = blockIdx.y * 128;
    const int col0  = blockIdx.x * 128;
    const int z     = (MODE == 0) ? blockIdx.z : 3;
    const float* Agm = (MODE == 0) ? (const float*)g_xc : (const float*)g_ctx;
    const float* Bgm = g_WT + (size_t)z * DM * DM;

    const int cm  = tid >> 3;
    const int ckq = tid & 7;
    const int g   = lane >> 2;
    const int t4  = lane & 3;

    const uint32_t base_u = smem_u32(dsm);

    auto issue = [&](int c, int stage) {
        const int kbase = c * 32 + ckq * 4;
        const uint32_t a_u = base_u + stage * 16384;
        const uint32_t b_u = base_u + 32768 + stage * 16384;
        #pragma unroll
        for (int t = 0; t < 4; t++) {
            int m = cm + t * 32;
            uint32_t off = (uint32_t)(m * 128 + ((ckq ^ (m & 7)) << 4));
            cp16(a_u + off, &Agm[(size_t)(row0 + m) * DM + kbase]);
            cp16(b_u + off, &Bgm[(size_t)(col0 + m) * DM + kbase]);
        }
    };

    float acc[4][4][4] = {};

    issue(0, 0); CP_COMMIT();
    issue(1, 1); CP_COMMIT();

    for (int c = 0; c < NC; c++) {
        CP_WAIT1();
        __syncthreads();

        const uint32_t* A  = dsm + (c & 1) * 4096;
        const uint32_t* Bm = dsm + 8192 + (c & 1) * 4096;

        #pragma unroll
        for (int kb = 0; kb < 4; kb++) {
            const int qlo = ((kb * 2 + 0) ^ g) << 2;
            const int qhi = ((kb * 2 + 1) ^ g) << 2;

            uint32_t a[4][4];
            #pragma unroll
            for (int mf = 0; mf < 4; mf++) {
                int mr = warpM * 64 + mf * 16;
                a[mf][0] = A[(mr + g)     * 32 + qlo + t4];
                a[mf][1] = A[(mr + 8 + g) * 32 + qlo + t4];
                a[mf][2] = A[(mr + g)     * 32 + qhi + t4];
                a[mf][3] = A[(mr + 8 + g) * 32 + qhi + t4];
            }
            uint32_t b[4][2];
            #pragma unroll
            for (int nf = 0; nf < 4; nf++) {
                int nr = warpN * 32 + nf * 8 + g;
                b[nf][0] = Bm[nr * 32 + qlo + t4];
                b[nf][1] = Bm[nr * 32 + qhi + t4];
            }
            #pragma unroll
            for (int mf = 0; mf < 4; mf++)
                #pragma unroll
                for (int nf = 0; nf < 4; nf++)
                    mma_tf32(acc[mf][nf], a[mf], b[nf][0], b[nf][1]);
        }
        __syncthreads();

        if (c + 2 < NC) issue(c + 2, c & 1);
        CP_COMMIT();
    }

    // ---- epilogue ----
    #pragma unroll
    for (int mf = 0; mf < 4; mf++) {
        #pragma unroll
        for (int half = 0; half < 2; half++) {
            int gr = row0 + warpM * 64 + mf * 16 + g + half * 8;
            int bb = gr >> 11, n = gr & (SEQ - 1);
            #pragma unroll
            for (int nf = 0; nf < 4; nf++) {
                int gc = col0 + warpN * 32 + nf * 8 + t4 * 2;
                float v0 = acc[mf][nf][half * 2 + 0];
                float v1 = acc[mf][nf][half * 2 + 1];
                if (MODE == 0) {
                    int h = gc >> 6, d = gc & 63;
                    size_t bh = (size_t)(bb * NH + h);
                    float* outs = (z == 0) ? g_Q : (z == 1) ? g_K : g_V;
                    *(float2*)&outs[(bh * SEQ + n) * HD + d]
                        = make_float2(rnd_tf32(v0), rnd_tf32(v1));
                } else {
                    float2 bv = *(const float2*)&bias[gc];
                    *(float2*)&Cout[(size_t)gr * DM + gc]
                        = make_float2(v0 + bv.x, v1 + bv.y);
                }
            }
        }
    }
}

// ---------------------------------------------------------------------------
// Flash attention (causal) via tf32 mma. 64 queries/block, 128 threads
// (4 warps x 16 query rows) so 2 CTAs co-reside per SM and overlap each
// other's softmax phases with mma. cp.async 2-stage double-buffered K/V.
// Dynamic smem: stage s: K at bytes s*32768, V at s*32768+16384 (64 KB).
// ---------------------------------------------------------------------------
__global__ __launch_bounds__(128, 2) void flash_mma()
{
    extern __shared__ __align__(16) uint32_t fsm[];

    const int tid  = threadIdx.x;
    const int lane = tid & 31;
    const int w    = tid >> 5;        // 0..3
    const int g    = lane >> 2;
    const int t    = lane & 3;

    const int qt = blockIdx.x;        // 0..31 (64-query tiles)
    const int h  = blockIdx.y;
    const int b  = blockIdx.z;
    const int q0 = qt * 64;
    const size_t bh = (size_t)(b * NH + h);

    const float* Qg = g_Q + bh * SEQ * HD;
    const float* Kg = g_K + bh * SEQ * HD;
    const float* Vg = g_V + bh * SEQ * HD;

    const int qrow0 = q0 + w * 16 + g;
    const int qrow1 = qrow0 + 8;

    const uint32_t base_u = smem_u32(fsm);

    auto issue_tile = [&](int kt, int stage) {
        const int k0  = kt * 64;
        const int rr0 = tid >> 4;          // 0..7
        const int cq  = (tid & 15) * 4;
        const uint32_t k_u = base_u + stage * 32768;
        const uint32_t v_u = k_u + 16384;
        #pragma unroll
        for (int i = 0; i < 8; i++) {
            int rr = rr0 + i * 8;
            uint32_t off = (uint32_t)SWA(rr, cq) * 4;
            cp16(k_u + off, &Kg[(size_t)(k0 + rr) * HD + cq]);
            cp16(v_u + off, &Vg[(size_t)(k0 + rr) * HD + cq]);
        }
    };

    // Q fragments: prescale by 0.125 (exact power of two; stays tf32)
    uint32_t qf[8][4];
    #pragma unroll
    for (int kb = 0; kb < 8; kb++) {
        qf[kb][0] = __float_as_uint(0.125f * Qg[(size_t)qrow0 * HD + kb * 8 + t]);
        qf[kb][1] = __float_as_uint(0.125f * Qg[(size_t)qrow1 * HD + kb * 8 + t]);
        qf[kb][2] = __float_as_uint(0.125f * Qg[(size_t)qrow0 * HD + kb * 8 + t + 4]);
        qf[kb][3] = __float_as_uint(0.125f * Qg[(size_t)qrow1 * HD + kb * 8 + t + 4]);
    }

    float o[8][4] = {};
    float m0 = -1e30f, m1 = -1e30f;
    float l0 = 0.f, l1 = 0.f;

    const int ntiles = qt + 1;         // always >= 1

    issue_tile(0, 0); CP_COMMIT();
    issue_tile(1, 1); CP_COMMIT();     // kt=1 may exceed ntiles; rows still in-bounds

    for (int kt = 0; kt < ntiles; kt++) {
        const int k0 = kt * 64;
        CP_WAIT1();
        __syncthreads();

        const uint32_t* sK = fsm + (kt & 1) * 8192;
        const uint32_t* sV = sK + 4096;

        // ---- S = Q @ K^T ----
        float s[8][4] = {};
        #pragma unroll
        for (int kb = 0; kb < 8; kb++) {
            #pragma unroll
            for (int nf = 0; nf < 8; nf++) {
                uint32_t b0 = sK[SWA(nf * 8 + g, kb * 8 + t)];
                uint32_t b1 = sK[SWA(nf * 8 + g, kb * 8 + t + 4)];
                mma_tf32(s[nf], qf[kb], b0, b1);
            }
        }

        // ---- causal mask (only near diagonal) + row max ----
        float mx0 = -1e30f, mx1 = -1e30f;
        if (k0 + 63 > qrow0) {
            #pragma unroll
            for (int nf = 0; nf < 8; nf++) {
                #pragma unroll
                for (int e = 0; e < 2; e++) {
                    int col = k0 + nf * 8 + 2 * t + e;
                    if (col > qrow0) s[nf][e]     = -1e30f;
                    if (col > qrow1) s[nf][2 + e] = -1e30f;
                    mx0 = fmaxf(mx0, s[nf][e]);
                    mx1 = fmaxf(mx1, s[nf][2 + e]);
                }
            }
        } else {
            #pragma unroll
            for (int nf = 0; nf < 8; nf++) {
                mx0 = fmaxf(mx0, fmaxf(s[nf][0], s[nf][1]));
                mx1 = fmaxf(mx1, fmaxf(s[nf][2], s[nf][3]));
            }
        }
        mx0 = fmaxf(mx0, __shfl_xor_sync(0xffffffffu, mx0, 1));
        mx0 = fmaxf(mx0, __shfl_xor_sync(0xffffffffu, mx0, 2));
        mx1 = fmaxf(mx1, __shfl_xor_sync(0xffffffffu, mx1, 1));
        mx1 = fmaxf(mx1, __shfl_xor_sync(0xffffffffu, mx1, 2));

        float nm0 = fmaxf(m0, mx0);
        float nm1 = fmaxf(m1, mx1);
        float c0 = __expf(m0 - nm0);
        float c1 = __expf(m1 - nm1);
        m0 = nm0; m1 = nm1;
        l0 *= c0; l1 *= c1;
        #pragma unroll
        for (int nf = 0; nf < 8; nf++) {
            o[nf][0] *= c0; o[nf][1] *= c0;
            o[nf][2] *= c1; o[nf][3] *= c1;
        }

        // ---- p = exp(s - m), lane-partial row sums ----
        #pragma unroll
        for (int nf = 0; nf < 8; nf++) {
            float p0 = __expf(s[nf][0] - m0);
            float p1 = __expf(s[nf][1] - m0);
            float p2 = __expf(s[nf][2] - m1);
            float p3 = __expf(s[nf][3] - m1);
            s[nf][0] = p0; s[nf][1] = p1; s[nf][2] = p2; s[nf][3] = p3;
            l0 += p0 + p1;
            l1 += p2 + p3;
        }

        // ---- PV: P C-frag -> A-frag via quad shuffles; B from sV swapped ----
        #pragma unroll
        for (int kb = 0; kb < 8; kb++) {
            const int s0 = (lane & ~3) | (t >> 1);
            const int s1 = s0 + 2;
            float lox0 = __shfl_sync(0xffffffffu, s[kb][0], s0);
            float loy0 = __shfl_sync(0xffffffffu, s[kb][1], s0);
            float hix0 = __shfl_sync(0xffffffffu, s[kb][2], s0);
            float hiy0 = __shfl_sync(0xffffffffu, s[kb][3], s0);
            float lox1 = __shfl_sync(0xffffffffu, s[kb][0], s1);
            float loy1 = __shfl_sync(0xffffffffu, s[kb][1], s1);
            float hix1 = __shfl_sync(0xffffffffu, s[kb][2], s1);
            float hiy1 = __shfl_sync(0xffffffffu, s[kb][3], s1);
            const bool e = (t & 1);
            uint32_t pa[4];
            pa[0] = f2tf32(e ? loy0 : lox0);
            pa[1] = f2tf32(e ? hiy0 : hix0);
            pa[2] = f2tf32(e ? loy1 : lox1);
            pa[3] = f2tf32(e ? hiy1 : hix1);

            #pragma unroll
            for (int nf = 0; nf < 8; nf++) {
                uint32_t b0 = sV[SWA(kb * 8 + t,     nf * 8 + g)];
                uint32_t b1 = sV[SWA(kb * 8 + t + 4, nf * 8 + g)];
                mma_tf32(o[nf], pa, b0, b1);
            }
        }
        __syncthreads();

        if (kt + 2 < ntiles) issue_tile(kt + 2, kt & 1);
        CP_COMMIT();
    }

    // ---- finalize (ctx written tf32-rounded for raw out_mma reads) ----
    l0 += __shfl_xor_sync(0xffffffffu, l0, 1);
    l0 += __shfl_xor_sync(0xffffffffu, l0, 2);
    l1 += __shfl_xor_sync(0xffffffffu, l1, 1);
    l1 += __shfl_xor_sync(0xffffffffu, l1, 2);
    const float inv0 = 1.f / l0;
    const float inv1 = 1.f / l1;

    #pragma unroll
    for (int nf = 0; nf < 8; nf++) {
        int dc = h * HD + nf * 8 + 2 * t;
        *(float2*)&g_ctx[(size_t)(b * SEQ + qrow0) * DM + dc]
            = make_float2(rnd_tf32(o[nf][0] * inv0), rnd_tf32(o[nf][1] * inv0));
        *(float2*)&g_ctx[(size_t)(b * SEQ + qrow1) * DM + dc]
            = make_float2(rnd_tf32(o[nf][2] * inv1), rnd_tf32(o[nf][3] * inv1));
    }
}

// ---------------------------------------------------------------------------
extern "C" void kernel_launch(void* const* d_in, const int* in_sizes, int n_in,
                              void* d_out, int out_size)
{
    const float* x  = (const float*)d_in[0];
    const float* Wq = (const float*)d_in[1];
    const float* Wk = (const float*)d_in[2];
    const float* Wv = (const float*)d_in[3];
    const float* Wo = (const float*)d_in[4];
    const float* bo = (const float*)d_in[5];
    float* out = (float*)d_out;

    cudaFuncSetAttribute(gemm_mma<0>, cudaFuncAttributeMaxDynamicSharedMemorySize, 65536);
    cudaFuncSetAttribute(gemm_mma<1>, cudaFuncAttributeMaxDynamicSharedMemorySize, 65536);
    cudaFuncSetAttribute(flash_mma,   cudaFuncAttributeMaxDynamicSharedMemorySize, 65536);

    cvt_x<<<2048, 256>>>(x);

    dim3 gt(32, 32, 4);
    transpose_w<<<gt, dim3(32, 8)>>>(Wq, Wk, Wv, Wo);

    dim3 g1(DM / 128, NTOK / 128, 3);      // 8 x 64 x 3
    gemm_mma<0><<<g1, 256, 65536>>>(nullptr, nullptr);

    dim3 g2(SEQ / 64, NH, B_);             // 32 x 16 x 4
    flash_mma<<<g2, 128, 65536>>>();

    dim3 g3(DM / 128, NTOK / 128);         // 8 x 64
    gemm_mma<1><<<g3, 256, 65536>>>(bo, out);
}

// round 15
// speedup vs baseline: 8.5089x; 1.0000x over previous
#include <cuda_runtime.h>
#include <cstdint>

#define B_    4
#define SEQ   2048
#define DM    1024
#define NH    16
#define HD    64
#define NTOK  (B_*SEQ)          // 8192
#define NC    (DM/32)           // 32 k-chunks

// ---------------------------------------------------------------------------
// Device scratch -- referenced ONLY inside kernels (round-3/6 lesson).
// All tf32-pre-rounded (rounding at producer makes every mma operand path a
// raw load; mma tf32 truncation is then lossless).
// ---------------------------------------------------------------------------
__device__ float g_xc[NTOK*DM];        // x pre-rounded to tf32
__device__ float g_Q[B_*NH*SEQ*HD];    // [b,h,n,d] tf32-rounded
__device__ float g_K[B_*NH*SEQ*HD];    // [b,h,n,d] tf32-rounded
__device__ float g_V[B_*NH*SEQ*HD];    // [b,h,n,d] tf32-rounded
__device__ float g_ctx[NTOK*DM];       // [token, D] tf32-rounded
__device__ float g_WT[4*DM*DM];        // W^T: [n][k], tf32-rounded

// ---------------------------------------------------------------------------
__device__ __forceinline__ uint32_t smem_u32(const void* p) {
    uint32_t a;
    asm("{ .reg .u64 t; cvta.to.shared.u64 t, %1; cvt.u32.u64 %0, t; }" : "=r"(a) : "l"(p));
    return a;
}

__device__ __forceinline__ uint32_t f2tf32(float x) {
    uint32_t u;
    asm("cvt.rna.tf32.f32 %0, %1;" : "=r"(u) : "f"(x));
    return u;
}
__device__ __forceinline__ float rnd_tf32(float x) {
    return __uint_as_float(f2tf32(x));
}

__device__ __forceinline__ void mma_tf32(float* d, const uint32_t* a,
                                         uint32_t b0, uint32_t b1) {
    asm volatile(
        "mma.sync.aligned.m16n8k8.row.col.f32.tf32.tf32.f32 "
        "{%0,%1,%2,%3}, {%4,%5,%6,%7}, {%8,%9}, {%0,%1,%2,%3};"
        : "+f"(d[0]), "+f"(d[1]), "+f"(d[2]), "+f"(d[3])
        : "r"(a[0]), "r"(a[1]), "r"(a[2]), "r"(a[3]), "r"(b0), "r"(b1));
}

__device__ __forceinline__ void cp16(uint32_t dst, const void* src) {
    asm volatile("cp.async.cg.shared.global [%0], [%1], 16;" :: "r"(dst), "l"(src));
}
#define CP_COMMIT() asm volatile("cp.async.commit_group;")
#define CP_WAIT1()  asm volatile("cp.async.wait_group 1;")

// 64-col-row swizzled smem addressing (two 32-word halves, quad-XOR swizzle)
__device__ __forceinline__ int SWA(int m, int k) {
    return m * 64 + (k & 32) + (((((k) >> 2) & 7) ^ (m & 7)) << 2) + (k & 3);
}

// ---------------------------------------------------------------------------
// x pre-round to tf32: g_xc = rna_tf32(x)
// ---------------------------------------------------------------------------
__global__ __launch_bounds__(256) void cvt_x(const float* __restrict__ x)
{
    const int i0 = (blockIdx.x * 256 + threadIdx.x) * 4;
    const int stride = gridDim.x * 256 * 4;
    for (int i = i0; i < NTOK * DM; i += stride) {
        float4 v = *(const float4*)&x[i];
        v.x = rnd_tf32(v.x); v.y = rnd_tf32(v.y);
        v.z = rnd_tf32(v.z); v.w = rnd_tf32(v.w);
        *(float4*)&g_xc[i] = v;
    }
}

// ---------------------------------------------------------------------------
// Weight transpose + tf32 round: g_WT[z][n][k] = rna_tf32(W_z[k][n])
// ---------------------------------------------------------------------------
__global__ __launch_bounds__(256) void transpose_w(
    const float* __restrict__ Wq, const float* __restrict__ Wk,
    const float* __restrict__ Wv, const float* __restrict__ Wo)
{
    __shared__ float t[32][33];
    const float* src = (blockIdx.z == 0) ? Wq : (blockIdx.z == 1) ? Wk :
                       (blockIdx.z == 2) ? Wv : Wo;
    float* dst = g_WT + (size_t)blockIdx.z * DM * DM;

    int tx = threadIdx.x, ty = threadIdx.y;
    int x0 = blockIdx.x * 32, y0 = blockIdx.y * 32;
    #pragma unroll
    for (int j = ty; j < 32; j += 8)
        t[j][tx] = src[(size_t)(y0 + j) * DM + x0 + tx];
    __syncthreads();
    #pragma unroll
    for (int j = ty; j < 32; j += 8)
        dst[(size_t)(x0 + j) * DM + y0 + tx] = rnd_tf32(t[tx][j]);
}

// ---------------------------------------------------------------------------
// TF32 mma GEMM, cp.async 2-stage pipeline, raw tf32-bit operands (no cvt).
// MODE 0: C = xc @ WT_z^T -> scatter g_Q/g_K/g_V (tf32-rounded at write).
// MODE 1: C = ctx @ WoT^T + bias -> out (full fp32).
// ---------------------------------------------------------------------------
template<int MODE>
__global__ __launch_bounds__(256, 2) void gemm_mma(
    const float* __restrict__ bias,
    float* __restrict__ Cout)
{
    extern __shared__ __align__(16) uint32_t dsm[];

    const int tid   = threadIdx.x;
    const int lane  = tid & 31;
    const int wid   = tid >> 5;
    const int warpM = wid & 1;
    const int warpN = wid >> 1;
    const int row0  = blockIdx.y * 128;
    const int col0  = blockIdx.x * 128;
    const int z     = (MODE == 0) ? blockIdx.z : 3;
    const float* Agm = (MODE == 0) ? (const float*)g_xc : (const float*)g_ctx;
    const float* Bgm = g_WT + (size_t)z * DM * DM;

    const int cm  = tid >> 3;
    const int ckq = tid & 7;
    const int g   = lane >> 2;
    const int t4  = lane & 3;

    const uint32_t base_u = smem_u32(dsm);

    auto issue = [&](int c, int stage) {
        const int kbase = c * 32 + ckq * 4;
        const uint32_t a_u = base_u + stage * 16384;
        const uint32_t b_u = base_u + 32768 + stage * 16384;
        #pragma unroll
        for (int t = 0; t < 4; t++) {
            int m = cm + t * 32;
            uint32_t off = (uint32_t)(m * 128 + ((ckq ^ (m & 7)) << 4));
            cp16(a_u + off, &Agm[(size_t)(row0 + m) * DM + kbase]);
            cp16(b_u + off, &Bgm[(size_t)(col0 + m) * DM + kbase]);
        }
    };

    float acc[4][4][4] = {};

    issue(0, 0); CP_COMMIT();
    issue(1, 1); CP_COMMIT();

    for (int c = 0; c < NC; c++) {
        CP_WAIT1();
        __syncthreads();

        const uint32_t* A  = dsm + (c & 1) * 4096;
        const uint32_t* Bm = dsm + 8192 + (c & 1) * 4096;

        #pragma unroll
        for (int kb = 0; kb < 4; kb++) {
            const int qlo = ((kb * 2 + 0) ^ g) << 2;
            const int qhi = ((kb * 2 + 1) ^ g) << 2;

            uint32_t a[4][4];
            #pragma unroll
            for (int mf = 0; mf < 4; mf++) {
                int mr = warpM * 64 + mf * 16;
                a[mf][0] = A[(mr + g)     * 32 + qlo + t4];
                a[mf][1] = A[(mr + 8 + g) * 32 + qlo + t4];
                a[mf][2] = A[(mr + g)     * 32 + qhi + t4];
                a[mf][3] = A[(mr + 8 + g) * 32 + qhi + t4];
            }
            uint32_t b[4][2];
            #pragma unroll
            for (int nf = 0; nf < 4; nf++) {
                int nr = warpN * 32 + nf * 8 + g;
                b[nf][0] = Bm[nr * 32 + qlo + t4];
                b[nf][1] = Bm[nr * 32 + qhi + t4];
            }
            #pragma unroll
            for (int mf = 0; mf < 4; mf++)
                #pragma unroll
                for (int nf = 0; nf < 4; nf++)
                    mma_tf32(acc[mf][nf], a[mf], b[nf][0], b[nf][1]);
        }
        __syncthreads();

        if (c + 2 < NC) issue(c + 2, c & 1);
        CP_COMMIT();
    }

    // ---- epilogue ----
    #pragma unroll
    for (int mf = 0; mf < 4; mf++) {
        #pragma unroll
        for (int half = 0; half < 2; half++) {
            int gr = row0 + warpM * 64 + mf * 16 + g + half * 8;
            int bb = gr >> 11, n = gr & (SEQ - 1);
            #pragma unroll
            for (int nf = 0; nf < 4; nf++) {
                int gc = col0 + warpN * 32 + nf * 8 + t4 * 2;
                float v0 = acc[mf][nf][half * 2 + 0];
                float v1 = acc[mf][nf][half * 2 + 1];
                if (MODE == 0) {
                    int h = gc >> 6, d = gc & 63;
                    size_t bh = (size_t)(bb * NH + h);
                    float* outs = (z == 0) ? g_Q : (z == 1) ? g_K : g_V;
                    *(float2*)&outs[(bh * SEQ + n) * HD + d]
                        = make_float2(rnd_tf32(v0), rnd_tf32(v1));
                } else {
                    float2 bv = *(const float2*)&bias[gc];
                    *(float2*)&Cout[(size_t)gr * DM + gc]
                        = make_float2(v0 + bv.x, v1 + bv.y);
                }
            }
        }
    }
}

// ---------------------------------------------------------------------------
// Flash attention (causal) via tf32 mma. 64 queries/block, 128 threads
// (4 warps x 16 query rows). launch_bounds(128,3) caps regs at 170 so THREE
// CTAs co-reside per SM (12 warps) to overlap softmax phases with mma.
// Work-descending block order: qt = gridDim.x-1-blockIdx.x (long CTAs first).
// cp.async 2-stage double-buffered K/V; stage s: K at bytes s*32768,
// V at s*32768+16384 (64 KB dynamic smem; 3 x 64 = 192 <= 228 KB).
// ---------------------------------------------------------------------------
__global__ __launch_bounds__(128, 3) void flash_mma()
{
    extern __shared__ __align__(16) uint32_t fsm[];

    const int tid  = threadIdx.x;
    const int lane = tid & 31;
    const int w    = tid >> 5;        // 0..3
    const int g    = lane >> 2;
    const int t    = lane & 3;

    const int qt = gridDim.x - 1 - blockIdx.x;   // descending work order
    const int h  = blockIdx.y;
    const int b  = blockIdx.z;
    const int q0 = qt * 64;
    const size_t bh = (size_t)(b * NH + h);

    const float* Qg = g_Q + bh * SEQ * HD;
    const float* Kg = g_K + bh * SEQ * HD;
    const float* Vg = g_V + bh * SEQ * HD;

    const int qrow0 = q0 + w * 16 + g;
    const int qrow1 = qrow0 + 8;

    const uint32_t base_u = smem_u32(fsm);

    auto issue_tile = [&](int kt, int stage) {
        const int k0  = kt * 64;
        const int rr0 = tid >> 4;          // 0..7
        const int cq  = (tid & 15) * 4;
        const uint32_t k_u = base_u + stage * 32768;
        const uint32_t v_u = k_u + 16384;
        #pragma unroll
        for (int i = 0; i < 8; i++) {
            int rr = rr0 + i * 8;
            uint32_t off = (uint32_t)SWA(rr, cq) * 4;
            cp16(k_u + off, &Kg[(size_t)(k0 + rr) * HD + cq]);
            cp16(v_u + off, &Vg[(size_t)(k0 + rr) * HD + cq]);
        }
    };

    // Q fragments: prescale by 0.125 (exact power of two; stays tf32)
    uint32_t qf[8][4];
    #pragma unroll
    for (int kb = 0; kb < 8; kb++) {
        qf[kb][0] = __float_as_uint(0.125f * Qg[(size_t)qrow0 * HD + kb * 8 + t]);
        qf[kb][1] = __float_as_uint(0.125f * Qg[(size_t)qrow1 * HD + kb * 8 + t]);
        qf[kb][2] = __float_as_uint(0.125f * Qg[(size_t)qrow0 * HD + kb * 8 + t + 4]);
        qf[kb][3] = __float_as_uint(0.125f * Qg[(size_t)qrow1 * HD + kb * 8 + t + 4]);
    }

    float o[8][4] = {};
    float m0 = -1e30f, m1 = -1e30f;
    float l0 = 0.f, l1 = 0.f;

    const int ntiles = qt + 1;         // always >= 1

    issue_tile(0, 0); CP_COMMIT();
    issue_tile(1, 1); CP_COMMIT();     // kt=1 may exceed ntiles; rows still in-bounds

    for (int kt = 0; kt < ntiles; kt++) {
        const int k0 = kt * 64;
        CP_WAIT1();
        __syncthreads();

        const uint32_t* sK = fsm + (kt & 1) * 8192;
        const uint32_t* sV = sK + 4096;

        // ---- S = Q @ K^T ----
        float s[8][4] = {};
        #pragma unroll
        for (int kb = 0; kb < 8; kb++) {
            #pragma unroll
            for (int nf = 0; nf < 8; nf++) {
                uint32_t b0 = sK[SWA(nf * 8 + g, kb * 8 + t)];
                uint32_t b1 = sK[SWA(nf * 8 + g, kb * 8 + t + 4)];
                mma_tf32(s[nf], qf[kb], b0, b1);
            }
        }

        // ---- causal mask (only near diagonal) + row max ----
        float mx0 = -1e30f, mx1 = -1e30f;
        if (k0 + 63 > qrow0) {
            #pragma unroll
            for (int nf = 0; nf < 8; nf++) {
                #pragma unroll
                for (int e = 0; e < 2; e++) {
                    int col = k0 + nf * 8 + 2 * t + e;
                    if (col > qrow0) s[nf][e]     = -1e30f;
                    if (col > qrow1) s[nf][2 + e] = -1e30f;
                    mx0 = fmaxf(mx0, s[nf][e]);
                    mx1 = fmaxf(mx1, s[nf][2 + e]);
                }
            }
        } else {
            #pragma unroll
            for (int nf = 0; nf < 8; nf++) {
                mx0 = fmaxf(mx0, fmaxf(s[nf][0], s[nf][1]));
                mx1 = fmaxf(mx1, fmaxf(s[nf][2], s[nf][3]));
            }
        }
        mx0 = fmaxf(mx0, __shfl_xor_sync(0xffffffffu, mx0, 1));
        mx0 = fmaxf(mx0, __shfl_xor_sync(0xffffffffu, mx0, 2));
        mx1 = fmaxf(mx1, __shfl_xor_sync(0xffffffffu, mx1, 1));
        mx1 = fmaxf(mx1, __shfl_xor_sync(0xffffffffu, mx1, 2));

        float nm0 = fmaxf(m0, mx0);
        float nm1 = fmaxf(m1, mx1);
        float c0 = __expf(m0 - nm0);
        float c1 = __expf(m1 - nm1);
        m0 = nm0; m1 = nm1;
        l0 *= c0; l1 *= c1;
        #pragma unroll
        for (int nf = 0; nf < 8; nf++) {
            o[nf][0] *= c0; o[nf][1] *= c0;
            o[nf][2] *= c1; o[nf][3] *= c1;
        }

        // ---- p = exp(s - m), lane-partial row sums ----
        #pragma unroll
        for (int nf = 0; nf < 8; nf++) {
            float p0 = __expf(s[nf][0] - m0);
            float p1 = __expf(s[nf][1] - m0);
            float p2 = __expf(s[nf][2] - m1);
            float p3 = __expf(s[nf][3] - m1);
            s[nf][0] = p0; s[nf][1] = p1; s[nf][2] = p2; s[nf][3] = p3;
            l0 += p0 + p1;
            l1 += p2 + p3;
        }

        // ---- PV: P C-frag -> A-frag via quad shuffles; B from sV swapped ----
        #pragma unroll
        for (int kb = 0; kb < 8; kb++) {
            const int s0 = (lane & ~3) | (t >> 1);
            const int s1 = s0 + 2;
            float lox0 = __shfl_sync(0xffffffffu, s[kb][0], s0);
            float loy0 = __shfl_sync(0xffffffffu, s[kb][1], s0);
            float hix0 = __shfl_sync(0xffffffffu, s[kb][2], s0);
            float hiy0 = __shfl_sync(0xffffffffu, s[kb][3], s0);
            float lox1 = __shfl_sync(0xffffffffu, s[kb][0], s1);
            float loy1 = __shfl_sync(0xffffffffu, s[kb][1], s1);
            float hix1 = __shfl_sync(0xffffffffu, s[kb][2], s1);
            float hiy1 = __shfl_sync(0xffffffffu, s[kb][3], s1);
            const bool e = (t & 1);
            uint32_t pa[4];
            pa[0] = f2tf32(e ? loy0 : lox0);
            pa[1] = f2tf32(e ? hiy0 : hix0);
            pa[2] = f2tf32(e ? loy1 : lox1);
            pa[3] = f2tf32(e ? hiy1 : hix1);

            #pragma unroll
            for (int nf = 0; nf < 8; nf++) {
                uint32_t b0 = sV[SWA(kb * 8 + t,     nf * 8 + g)];
                uint32_t b1 = sV[SWA(kb * 8 + t + 4, nf * 8 + g)];
                mma_tf32(o[nf], pa, b0, b1);
            }
        }
        __syncthreads();

        if (kt + 2 < ntiles) issue_tile(kt + 2, kt & 1);
        CP_COMMIT();
    }

    // ---- finalize (ctx written tf32-rounded for raw out_mma reads) ----
    l0 += __shfl_xor_sync(0xffffffffu, l0, 1);
    l0 += __shfl_xor_sync(0xffffffffu, l0, 2);
    l1 += __shfl_xor_sync(0xffffffffu, l1, 1);
    l1 += __shfl_xor_sync(0xffffffffu, l1, 2);
    const float inv0 = 1.f / l0;
    const float inv1 = 1.f / l1;

    #pragma unroll
    for (int nf = 0; nf < 8; nf++) {
        int dc = h * HD + nf * 8 + 2 * t;
        *(float2*)&g_ctx[(size_t)(b * SEQ + qrow0) * DM + dc]
            = make_float2(rnd_tf32(o[nf][0] * inv0), rnd_tf32(o[nf][1] * inv0));
        *(float2*)&g_ctx[(size_t)(b * SEQ + qrow1) * DM + dc]
            = make_float2(rnd_tf32(o[nf][2] * inv1), rnd_tf32(o[nf][3] * inv1));
    }
}

// ---------------------------------------------------------------------------
extern "C" void kernel_launch(void* const* d_in, const int* in_sizes, int n_in,
                              void* d_out, int out_size)
{
    const float* x  = (const float*)d_in[0];
    const float* Wq = (const float*)d_in[1];
    const float* Wk = (const float*)d_in[2];
    const float* Wv = (const float*)d_in[3];
    const float* Wo = (const float*)d_in[4];
    const float* bo = (const float*)d_in[5];
    float* out = (float*)d_out;

    cudaFuncSetAttribute(gemm_mma<0>, cudaFuncAttributeMaxDynamicSharedMemorySize, 65536);
    cudaFuncSetAttribute(gemm_mma<1>, cudaFuncAttributeMaxDynamicSharedMemorySize, 65536);
    cudaFuncSetAttribute(flash_mma,   cudaFuncAttributeMaxDynamicSharedMemorySize, 65536);

    cvt_x<<<2048, 256>>>(x);

    dim3 gt(32, 32, 4);
    transpose_w<<<gt, dim3(32, 8)>>>(Wq, Wk, Wv, Wo);

    dim3 g1(DM / 128, NTOK / 128, 3);      // 8 x 64 x 3
    gemm_mma<0><<<g1, 256, 65536>>>(nullptr, nullptr);

    dim3 g2(SEQ / 64, NH, B_);             // 32 x 16 x 4
    flash_mma<<<g2, 128, 65536>>>();

    dim3 g3(DM / 128, NTOK / 128);         // 8 x 64
    gemm_mma<1><<<g3, 256, 65536>>>(bo, out);
}

// round 16
// speedup vs baseline: 11.0908x; 1.3034x over previous
#include <cuda_runtime.h>
#include <cuda_fp16.h>
#include <cstdint>

#define B_    4
#define SEQ   2048
#define DM    1024
#define NH    16
#define HD    64
#define NTOK  (B_*SEQ)          // 8192
#define NC    (DM/32)           // 32 k-chunks

// ---------------------------------------------------------------------------
// Device scratch -- referenced ONLY inside kernels (round-3/6 lesson).
// GEMM operands tf32-pre-rounded; flash operands fp16 (written by qkv epi).
// ---------------------------------------------------------------------------
__device__ float  g_xc[NTOK*DM];         // x pre-rounded to tf32
__device__ __half g_Qh[B_*NH*SEQ*HD];    // [b,h,n,d] fp16, PRE-SCALED by 0.125
__device__ __half g_Kh[B_*NH*SEQ*HD];    // [b,h,n,d] fp16
__device__ __half g_VTh[B_*NH*HD*SEQ];   // [b,h,d,n] fp16 (PV B-operand)
__device__ float  g_ctx[NTOK*DM];        // [token, D] tf32-rounded
__device__ float  g_WT[4*DM*DM];         // W^T: [n][k], tf32-rounded

// ---------------------------------------------------------------------------
__device__ __forceinline__ uint32_t smem_u32(const void* p) {
    uint32_t a;
    asm("{ .reg .u64 t; cvta.to.shared.u64 t, %1; cvt.u32.u64 %0, t; }" : "=r"(a) : "l"(p));
    return a;
}

__device__ __forceinline__ uint32_t f2tf32(float x) {
    uint32_t u;
    asm("cvt.rna.tf32.f32 %0, %1;" : "=r"(u) : "f"(x));
    return u;
}
__device__ __forceinline__ float rnd_tf32(float x) {
    return __uint_as_float(f2tf32(x));
}
__device__ __forceinline__ uint32_t packh2(float lo, float hi) {
    __half2 h = __floats2half2_rn(lo, hi);
    return *(uint32_t*)&h;
}

__device__ __forceinline__ void mma_tf32(float* d, const uint32_t* a,
                                         uint32_t b0, uint32_t b1) {
    asm volatile(
        "mma.sync.aligned.m16n8k8.row.col.f32.tf32.tf32.f32 "
        "{%0,%1,%2,%3}, {%4,%5,%6,%7}, {%8,%9}, {%0,%1,%2,%3};"
        : "+f"(d[0]), "+f"(d[1]), "+f"(d[2]), "+f"(d[3])
        : "r"(a[0]), "r"(a[1]), "r"(a[2]), "r"(a[3]), "r"(b0), "r"(b1));
}

__device__ __forceinline__ void mma_f16(float* d, const uint32_t* a,
                                        uint32_t b0, uint32_t b1) {
    asm volatile(
        "mma.sync.aligned.m16n8k16.row.col.f32.f16.f16.f32 "
        "{%0,%1,%2,%3}, {%4,%5,%6,%7}, {%8,%9}, {%0,%1,%2,%3};"
        : "+f"(d[0]), "+f"(d[1]), "+f"(d[2]), "+f"(d[3])
        : "r"(a[0]), "r"(a[1]), "r"(a[2]), "r"(a[3]), "r"(b0), "r"(b1));
}

__device__ __forceinline__ void cp16(uint32_t dst, const void* src) {
    asm volatile("cp.async.cg.shared.global [%0], [%1], 16;" :: "r"(dst), "l"(src));
}
#define CP_COMMIT() asm volatile("cp.async.commit_group;")
#define CP_WAIT1()  asm volatile("cp.async.wait_group 1;")

// 64-col-row swizzled smem addressing for fp32 GEMM tiles
__device__ __forceinline__ int SWA(int m, int k) {
    return m * 64 + (k & 32) + (((((k) >> 2) & 7) ^ (m & 7)) << 2) + (k & 3);
}

// ---------------------------------------------------------------------------
// x pre-round to tf32: g_xc = rna_tf32(x)
// ---------------------------------------------------------------------------
__global__ __launch_bounds__(256) void cvt_x(const float* __restrict__ x)
{
    const int i0 = (blockIdx.x * 256 + threadIdx.x) * 4;
    const int stride = gridDim.x * 256 * 4;
    for (int i = i0; i < NTOK * DM; i += stride) {
        float4 v = *(const float4*)&x[i];
        v.x = rnd_tf32(v.x); v.y = rnd_tf32(v.y);
        v.z = rnd_tf32(v.z); v.w = rnd_tf32(v.w);
        *(float4*)&g_xc[i] = v;
    }
}

// ---------------------------------------------------------------------------
// Weight transpose + tf32 round: g_WT[z][n][k] = rna_tf32(W_z[k][n])
// ---------------------------------------------------------------------------
__global__ __launch_bounds__(256) void transpose_w(
    const float* __restrict__ Wq, const float* __restrict__ Wk,
    const float* __restrict__ Wv, const float* __restrict__ Wo)
{
    __shared__ float t[32][33];
    const float* src = (blockIdx.z == 0) ? Wq : (blockIdx.z == 1) ? Wk :
                       (blockIdx.z == 2) ? Wv : Wo;
    float* dst = g_WT + (size_t)blockIdx.z * DM * DM;

    int tx = threadIdx.x, ty = threadIdx.y;
    int x0 = blockIdx.x * 32, y0 = blockIdx.y * 32;
    #pragma unroll
    for (int j = ty; j < 32; j += 8)
        t[j][tx] = src[(size_t)(y0 + j) * DM + x0 + tx];
    __syncthreads();
    #pragma unroll
    for (int j = ty; j < 32; j += 8)
        dst[(size_t)(x0 + j) * DM + y0 + tx] = rnd_tf32(t[tx][j]);
}

// ---------------------------------------------------------------------------
// TF32 mma GEMM, cp.async 2-stage pipeline, raw tf32-bit operands.
// MODE 0: C = xc @ WT_z^T -> half scatter: z=0 Qh (x0.125), z=1 Kh, z=2 VTh.
// MODE 1: C = ctx @ WoT^T + bias -> out (full fp32).
// ---------------------------------------------------------------------------
template<int MODE>
__global__ __launch_bounds__(256, 2) void gemm_mma(
    const float* __restrict__ bias,
    float* __restrict__ Cout)
{
    extern __shared__ __align__(16) uint32_t dsm[];

    const int tid   = threadIdx.x;
    const int lane  = tid & 31;
    const int wid   = tid >> 5;
    const int warpM = wid & 1;
    const int warpN = wid >> 1;
    const int row0  = blockIdx.y * 128;
    const int col0  = blockIdx.x * 128;
    const int z     = (MODE == 0) ? blockIdx.z : 3;
    const float* Agm = (MODE == 0) ? (const float*)g_xc : (const float*)g_ctx;
    const float* Bgm = g_WT + (size_t)z * DM * DM;

    const int cm  = tid >> 3;
    const int ckq = tid & 7;
    const int g   = lane >> 2;
    const int t4  = lane & 3;

    const uint32_t base_u = smem_u32(dsm);

    auto issue = [&](int c, int stage) {
        const int kbase = c * 32 + ckq * 4;
        const uint32_t a_u = base_u + stage * 16384;
        const uint32_t b_u = base_u + 32768 + stage * 16384;
        #pragma unroll
        for (int t = 0; t < 4; t++) {
            int m = cm + t * 32;
            uint32_t off = (uint32_t)(m * 128 + ((ckq ^ (m & 7)) << 4));
            cp16(a_u + off, &Agm[(size_t)(row0 + m) * DM + kbase]);
            cp16(b_u + off, &Bgm[(size_t)(col0 + m) * DM + kbase]);
        }
    };

    float acc[4][4][4] = {};

    issue(0, 0); CP_COMMIT();
    issue(1, 1); CP_COMMIT();

    for (int c = 0; c < NC; c++) {
        CP_WAIT1();
        __syncthreads();

        const uint32_t* A  = dsm + (c & 1) * 4096;
        const uint32_t* Bm = dsm + 8192 + (c & 1) * 4096;

        #pragma unroll
        for (int kb = 0; kb < 4; kb++) {
            const int qlo = ((kb * 2 + 0) ^ g) << 2;
            const int qhi = ((kb * 2 + 1) ^ g) << 2;

            uint32_t a[4][4];
            #pragma unroll
            for (int mf = 0; mf < 4; mf++) {
                int mr = warpM * 64 + mf * 16;
                a[mf][0] = A[(mr + g)     * 32 + qlo + t4];
                a[mf][1] = A[(mr + 8 + g) * 32 + qlo + t4];
                a[mf][2] = A[(mr + g)     * 32 + qhi + t4];
                a[mf][3] = A[(mr + 8 + g) * 32 + qhi + t4];
            }
            uint32_t b[4][2];
            #pragma unroll
            for (int nf = 0; nf < 4; nf++) {
                int nr = warpN * 32 + nf * 8 + g;
                b[nf][0] = Bm[nr * 32 + qlo + t4];
                b[nf][1] = Bm[nr * 32 + qhi + t4];
            }
            #pragma unroll
            for (int mf = 0; mf < 4; mf++)
                #pragma unroll
                for (int nf = 0; nf < 4; nf++)
                    mma_tf32(acc[mf][nf], a[mf], b[nf][0], b[nf][1]);
        }
        __syncthreads();

        if (c + 2 < NC) issue(c + 2, c & 1);
        CP_COMMIT();
    }

    // ---- epilogue ----
    #pragma unroll
    for (int mf = 0; mf < 4; mf++) {
        #pragma unroll
        for (int half = 0; half < 2; half++) {
            int gr = row0 + warpM * 64 + mf * 16 + g + half * 8;
            int bb = gr >> 11, n = gr & (SEQ - 1);
            #pragma unroll
            for (int nf = 0; nf < 4; nf++) {
                int gc = col0 + warpN * 32 + nf * 8 + t4 * 2;
                float v0 = acc[mf][nf][half * 2 + 0];
                float v1 = acc[mf][nf][half * 2 + 1];
                if (MODE == 0) {
                    int h = gc >> 6, d = gc & 63;
                    size_t bh = (size_t)(bb * NH + h);
                    if (z == 0) {
                        __half2 hv = __floats2half2_rn(v0 * 0.125f, v1 * 0.125f);
                        *(__half2*)&g_Qh[(bh * SEQ + n) * HD + d] = hv;
                    } else if (z == 1) {
                        __half2 hv = __floats2half2_rn(v0, v1);
                        *(__half2*)&g_Kh[(bh * SEQ + n) * HD + d] = hv;
                    } else {
                        g_VTh[(bh * HD + d)     * SEQ + n] = __float2half_rn(v0);
                        g_VTh[(bh * HD + d + 1) * SEQ + n] = __float2half_rn(v1);
                    }
                } else {
                    float2 bv = *(const float2*)&bias[gc];
                    *(float2*)&Cout[(size_t)gr * DM + gc]
                        = make_float2(v0 + bv.x, v1 + bv.y);
                }
            }
        }
    }
}

// ---------------------------------------------------------------------------
// Flash attention (causal) via fp16 m16n8k16 mma. 64 queries/block,
// 128 threads (4 warps x 16 query rows). S C-frag layout == PV A-frag
// layout (k16 fp16 property) -> zero shuffles; P packs in-lane.
// Tiles: K [64 key x 64 d] half 8KB, VT [64 d x 64 key] half 8KB.
// Swizzle: 16B chunk c of row r stored at chunk (c XOR (r&7)).
// cp.async 2-stage: stage s: K at bytes s*16384, VT at s*16384+8192.
// ---------------------------------------------------------------------------
__global__ __launch_bounds__(128, 3) void flash_mma()
{
    extern __shared__ __align__(16) uint32_t fsm[];

    const int tid  = threadIdx.x;
    const int lane = tid & 31;
    const int w    = tid >> 5;        // 0..3
    const int g    = lane >> 2;
    const int t    = lane & 3;

    const int qt = gridDim.x - 1 - blockIdx.x;   // descending work order
    const int h  = blockIdx.y;
    const int b  = blockIdx.z;
    const int q0 = qt * 64;
    const size_t bh = (size_t)(b * NH + h);

    const __half* Qh  = g_Qh  + bh * SEQ * HD;
    const __half* Kh  = g_Kh  + bh * SEQ * HD;
    const __half* VTh = g_VTh + bh * HD * SEQ;

    const int qrow0 = q0 + w * 16 + g;
    const int qrow1 = qrow0 + 8;

    const uint32_t base_u = smem_u32(fsm);
    const char* smc = (const char*)fsm;

    auto issue_tile = [&](int kt, int stage) {
        const int k0 = kt * 64;
        const int c  = tid & 7;            // 16B chunk within 128B row
        const uint32_t k_u = base_u + stage * 16384;
        const uint32_t v_u = k_u + 8192;
        #pragma unroll
        for (int i = 0; i < 4; i++) {
            int rr = (tid >> 3) + i * 16;  // 0..63
            uint32_t off = (uint32_t)(rr * 128 + ((c ^ (rr & 7)) << 4));
            cp16(k_u + off, Kh  + (size_t)(k0 + rr) * HD + c * 8);
            cp16(v_u + off, VTh + (size_t)rr * SEQ + k0 + c * 8);
        }
    };

    // Q fragments (fp16, pre-scaled by 0.125 at qkv epilogue)
    uint32_t qf[4][4];
    #pragma unroll
    for (int kb = 0; kb < 4; kb++) {
        qf[kb][0] = *(const uint32_t*)(Qh + (size_t)qrow0 * HD + kb * 16 + 2 * t);
        qf[kb][1] = *(const uint32_t*)(Qh + (size_t)qrow1 * HD + kb * 16 + 2 * t);
        qf[kb][2] = *(const uint32_t*)(Qh + (size_t)qrow0 * HD + kb * 16 + 2 * t + 8);
        qf[kb][3] = *(const uint32_t*)(Qh + (size_t)qrow1 * HD + kb * 16 + 2 * t + 8);
    }

    float o[8][4] = {};
    float m0 = -1e30f, m1 = -1e30f;
    float l0 = 0.f, l1 = 0.f;

    const int ntiles = qt + 1;

    issue_tile(0, 0); CP_COMMIT();
    issue_tile(1, 1); CP_COMMIT();     // kt=1 rows always in-bounds (SEQ=2048)

    for (int kt = 0; kt < ntiles; kt++) {
        const int k0 = kt * 64;
        CP_WAIT1();
        __syncthreads();

        const char* sKc = smc + (kt & 1) * 16384;
        const char* sVc = sKc + 8192;

        // ---- S = Q @ K^T (4 k16-steps x 8 key-blocks) ----
        float s[8][4] = {};
        #pragma unroll
        for (int kb = 0; kb < 4; kb++) {
            const int c0 = ((2 * kb)     ) << 4;
            const int c1 = ((2 * kb + 1) ) << 4;
            #pragma unroll
            for (int nf = 0; nf < 8; nf++) {
                int row = nf * 8 + g;
                int rb  = row * 128 + 4 * t;
                int swz = (g << 4);
                uint32_t b0 = *(const uint32_t*)(sKc + rb + (c0 ^ swz));
                uint32_t b1 = *(const uint32_t*)(sKc + rb + (c1 ^ swz));
                mma_f16(s[nf], qf[kb], b0, b1);
            }
        }

        // ---- causal mask (only near diagonal) + row max ----
        float mx0 = -1e30f, mx1 = -1e30f;
        if (k0 + 63 > qrow0) {
            #pragma unroll
            for (int nf = 0; nf < 8; nf++) {
                #pragma unroll
                for (int e = 0; e < 2; e++) {
                    int col = k0 + nf * 8 + 2 * t + e;
                    if (col > qrow0) s[nf][e]     = -1e30f;
                    if (col > qrow1) s[nf][2 + e] = -1e30f;
                    mx0 = fmaxf(mx0, s[nf][e]);
                    mx1 = fmaxf(mx1, s[nf][2 + e]);
                }
            }
        } else {
            #pragma unroll
            for (int nf = 0; nf < 8; nf++) {
                mx0 = fmaxf(mx0, fmaxf(s[nf][0], s[nf][1]));
                mx1 = fmaxf(mx1, fmaxf(s[nf][2], s[nf][3]));
            }
        }
        mx0 = fmaxf(mx0, __shfl_xor_sync(0xffffffffu, mx0, 1));
        mx0 = fmaxf(mx0, __shfl_xor_sync(0xffffffffu, mx0, 2));
        mx1 = fmaxf(mx1, __shfl_xor_sync(0xffffffffu, mx1, 1));
        mx1 = fmaxf(mx1, __shfl_xor_sync(0xffffffffu, mx1, 2));

        float nm0 = fmaxf(m0, mx0);
        float nm1 = fmaxf(m1, mx1);
        float c0s = __expf(m0 - nm0);
        float c1s = __expf(m1 - nm1);
        m0 = nm0; m1 = nm1;
        l0 *= c0s; l1 *= c1s;
        #pragma unroll
        for (int nf = 0; nf < 8; nf++) {
            o[nf][0] *= c0s; o[nf][1] *= c0s;
            o[nf][2] *= c1s; o[nf][3] *= c1s;
        }

        // ---- p = exp(s - m), lane-partial row sums ----
        #pragma unroll
        for (int nf = 0; nf < 8; nf++) {
            float p0 = __expf(s[nf][0] - m0);
            float p1 = __expf(s[nf][1] - m0);
            float p2 = __expf(s[nf][2] - m1);
            float p3 = __expf(s[nf][3] - m1);
            s[nf][0] = p0; s[nf][1] = p1; s[nf][2] = p2; s[nf][3] = p3;
            l0 += p0 + p1;
            l1 += p2 + p3;
        }

        // ---- PV: in-lane P pack (C-frag == A-frag for fp16 k16) ----
        #pragma unroll
        for (int kb = 0; kb < 4; kb++) {
            uint32_t pa[4];
            pa[0] = packh2(s[2*kb][0],     s[2*kb][1]);
            pa[1] = packh2(s[2*kb][2],     s[2*kb][3]);
            pa[2] = packh2(s[2*kb + 1][0], s[2*kb + 1][1]);
            pa[3] = packh2(s[2*kb + 1][2], s[2*kb + 1][3]);

            const int c0 = ((2 * kb)     ) << 4;
            const int c1 = ((2 * kb + 1) ) << 4;
            #pragma unroll
            for (int nf = 0; nf < 8; nf++) {
                int row = nf * 8 + g;     // d-row of VT
                int rb  = row * 128 + 4 * t;
                int swz = (g << 4);
                uint32_t b0 = *(const uint32_t*)(sVc + rb + (c0 ^ swz));
                uint32_t b1 = *(const uint32_t*)(sVc + rb + (c1 ^ swz));
                mma_f16(o[nf], pa, b0, b1);
            }
        }
        __syncthreads();

        if (kt + 2 < ntiles) issue_tile(kt + 2, kt & 1);
        CP_COMMIT();
    }

    // ---- finalize (ctx written tf32-rounded for raw out_mma reads) ----
    l0 += __shfl_xor_sync(0xffffffffu, l0, 1);
    l0 += __shfl_xor_sync(0xffffffffu, l0, 2);
    l1 += __shfl_xor_sync(0xffffffffu, l1, 1);
    l1 += __shfl_xor_sync(0xffffffffu, l1, 2);
    const float inv0 = 1.f / l0;
    const float inv1 = 1.f / l1;

    #pragma unroll
    for (int nf = 0; nf < 8; nf++) {
        int dc = h * HD + nf * 8 + 2 * t;
        *(float2*)&g_ctx[(size_t)(b * SEQ + qrow0) * DM + dc]
            = make_float2(rnd_tf32(o[nf][0] * inv0), rnd_tf32(o[nf][1] * inv0));
        *(float2*)&g_ctx[(size_t)(b * SEQ + qrow1) * DM + dc]
            = make_float2(rnd_tf32(o[nf][2] * inv1), rnd_tf32(o[nf][3] * inv1));
    }
}

// ---------------------------------------------------------------------------
extern "C" void kernel_launch(void* const* d_in, const int* in_sizes, int n_in,
                              void* d_out, int out_size)
{
    const float* x  = (const float*)d_in[0];
    const float* Wq = (const float*)d_in[1];
    const float* Wk = (const float*)d_in[2];
    const float* Wv = (const float*)d_in[3];
    const float* Wo = (const float*)d_in[4];
    const float* bo = (const float*)d_in[5];
    float* out = (float*)d_out;

    cudaFuncSetAttribute(gemm_mma<0>, cudaFuncAttributeMaxDynamicSharedMemorySize, 65536);
    cudaFuncSetAttribute(gemm_mma<1>, cudaFuncAttributeMaxDynamicSharedMemorySize, 65536);
    cudaFuncSetAttribute(flash_mma,   cudaFuncAttributeMaxDynamicSharedMemorySize, 32768);

    cvt_x<<<2048, 256>>>(x);

    dim3 gt(32, 32, 4);
    transpose_w<<<gt, dim3(32, 8)>>>(Wq, Wk, Wv, Wo);

    dim3 g1(DM / 128, NTOK / 128, 3);      // 8 x 64 x 3
    gemm_mma<0><<<g1, 256, 65536>>>(nullptr, nullptr);

    dim3 g2(SEQ / 64, NH, B_);             // 32 x 16 x 4
    flash_mma<<<g2, 128, 32768>>>();

    dim3 g3(DM / 128, NTOK / 128);         // 8 x 64
    gemm_mma<1><<<g3, 256, 65536>>>(bo, out);
}

// round 17
// speedup vs baseline: 17.0713x; 1.5392x over previous
#include <cuda_runtime.h>
#include <cuda_fp16.h>
#include <cstdint>

#define B_    4
#define SEQ   2048
#define DM    1024
#define NH    16
#define HD    64
#define NTOK  (B_*SEQ)          // 8192
#define NCH   (DM/64)           // 16 k-chunks of 64 (fp16 GEMM)

// ---------------------------------------------------------------------------
// Device scratch -- referenced ONLY inside kernels (round-3/6 lesson).
// Everything fp16 operands + fp32 accumulate end-to-end.
// ---------------------------------------------------------------------------
__device__ __half g_xh[NTOK*DM];         // x rounded to fp16
__device__ __half g_Qh[B_*NH*SEQ*HD];    // [b,h,n,d] fp16, PRE-SCALED by 0.125
__device__ __half g_Kh[B_*NH*SEQ*HD];    // [b,h,n,d] fp16
__device__ __half g_VTh[B_*NH*HD*SEQ];   // [b,h,d,n] fp16 (PV B-operand)
__device__ __half g_ctxh[NTOK*DM];       // [token, D] fp16
__device__ __half g_WTh[4*DM*DM];        // W^T: [n][k] fp16 (q,k,v,o)

// ---------------------------------------------------------------------------
__device__ __forceinline__ uint32_t smem_u32(const void* p) {
    uint32_t a;
    asm("{ .reg .u64 t; cvta.to.shared.u64 t, %1; cvt.u32.u64 %0, t; }" : "=r"(a) : "l"(p));
    return a;
}

__device__ __forceinline__ uint32_t packh2(float lo, float hi) {
    __half2 h = __floats2half2_rn(lo, hi);
    return *(uint32_t*)&h;
}

__device__ __forceinline__ void mma_f16(float* d, const uint32_t* a,
                                        uint32_t b0, uint32_t b1) {
    asm volatile(
        "mma.sync.aligned.m16n8k16.row.col.f32.f16.f16.f32 "
        "{%0,%1,%2,%3}, {%4,%5,%6,%7}, {%8,%9}, {%0,%1,%2,%3};"
        : "+f"(d[0]), "+f"(d[1]), "+f"(d[2]), "+f"(d[3])
        : "r"(a[0]), "r"(a[1]), "r"(a[2]), "r"(a[3]), "r"(b0), "r"(b1));
}

__device__ __forceinline__ void cp16(uint32_t dst, const void* src) {
    asm volatile("cp.async.cg.shared.global [%0], [%1], 16;" :: "r"(dst), "l"(src));
}
#define CP_COMMIT() asm volatile("cp.async.commit_group;")
#define CP_WAIT1()  asm volatile("cp.async.wait_group 1;")

// ---------------------------------------------------------------------------
// x round to fp16: g_xh = half(x)
// ---------------------------------------------------------------------------
__global__ __launch_bounds__(256) void cvt_x(const float* __restrict__ x)
{
    const int i0 = (blockIdx.x * 256 + threadIdx.x) * 8;
    const int stride = gridDim.x * 256 * 8;
    for (int i = i0; i < NTOK * DM; i += stride) {
        float4 v0 = *(const float4*)&x[i];
        float4 v1 = *(const float4*)&x[i + 4];
        uint4 o;
        o.x = packh2(v0.x, v0.y);
        o.y = packh2(v0.z, v0.w);
        o.z = packh2(v1.x, v1.y);
        o.w = packh2(v1.z, v1.w);
        *(uint4*)&g_xh[i] = o;
    }
}

// ---------------------------------------------------------------------------
// Weight transpose + fp16 round: g_WTh[z][n][k] = half(W_z[k][n])
// ---------------------------------------------------------------------------
__global__ __launch_bounds__(256) void transpose_w(
    const float* __restrict__ Wq, const float* __restrict__ Wk,
    const float* __restrict__ Wv, const float* __restrict__ Wo)
{
    __shared__ float t[32][33];
    const float* src = (blockIdx.z == 0) ? Wq : (blockIdx.z == 1) ? Wk :
                       (blockIdx.z == 2) ? Wv : Wo;
    __half* dst = g_WTh + (size_t)blockIdx.z * DM * DM;

    int tx = threadIdx.x, ty = threadIdx.y;
    int x0 = blockIdx.x * 32, y0 = blockIdx.y * 32;
    #pragma unroll
    for (int j = ty; j < 32; j += 8)
        t[j][tx] = src[(size_t)(y0 + j) * DM + x0 + tx];
    __syncthreads();
    #pragma unroll
    for (int j = ty; j < 32; j += 8)
        dst[(size_t)(x0 + j) * DM + y0 + tx] = __float2half_rn(t[tx][j]);
}

// ---------------------------------------------------------------------------
// FP16 m16n8k16 GEMM, cp.async 2-stage, BK=64 (128B half rows, chunk-XOR
// swizzle -- same scheme validated in flash). 128x128 tile, 8 warps (2Mx4N).
// MODE 0: C = xh @ WTh_z^T -> scatter: z=0 Qh (x0.125), z=1 Kh, z=2 VTh.
// MODE 1: C = ctxh @ WTh_o^T + bias -> out (fp32).
// Smem bytes: stage s: A at s*16384, B at 32768 + s*16384 (64 KB total).
// ---------------------------------------------------------------------------
template<int MODE>
__global__ __launch_bounds__(256, 2) void gemm_mma(
    const float* __restrict__ bias,
    float* __restrict__ Cout)
{
    extern __shared__ __align__(16) char dsm[];

    const int tid   = threadIdx.x;
    const int lane  = tid & 31;
    const int wid   = tid >> 5;
    const int warpM = wid & 1;
    const int warpN = wid >> 1;
    const int row0  = blockIdx.y * 128;
    const int col0  = blockIdx.x * 128;
    const int z     = (MODE == 0) ? blockIdx.z : 3;
    const __half* Agm = (MODE == 0) ? (const __half*)g_xh : (const __half*)g_ctxh;
    const __half* Bgm = g_WTh + (size_t)z * DM * DM;

    const int g  = lane >> 2;
    const int t  = lane & 3;
    const int cc = tid & 7;          // copy chunk (16B) within 128B row
    const int cr = tid >> 3;         // copy row base (0..31), +32 per iter

    const uint32_t base_u = smem_u32(dsm);

    auto issue = [&](int c, int stage) {
        const int kbase = c * 64 + cc * 8;     // halves
        const uint32_t a_u = base_u + stage * 16384;
        const uint32_t b_u = base_u + 32768 + stage * 16384;
        #pragma unroll
        for (int i = 0; i < 4; i++) {
            int m = cr + i * 32;
            uint32_t off = (uint32_t)(m * 128 + ((cc ^ (m & 7)) << 4));
            cp16(a_u + off, Agm + (size_t)(row0 + m) * DM + kbase);
            cp16(b_u + off, Bgm + (size_t)(col0 + m) * DM + kbase);
        }
    };

    float acc[4][4][4] = {};

    issue(0, 0); CP_COMMIT();
    issue(1, 1); CP_COMMIT();

    const int swz = g << 4;

    for (int c = 0; c < NCH; c++) {
        CP_WAIT1();
        __syncthreads();

        const char* A  = dsm + (c & 1) * 16384;
        const char* Bm = dsm + 32768 + (c & 1) * 16384;

        #pragma unroll
        for (int ks = 0; ks < 4; ks++) {
            const int c0 = ((2 * ks)     << 4) ^ swz;
            const int c1 = ((2 * ks + 1) << 4) ^ swz;

            uint32_t a[4][4];
            #pragma unroll
            for (int mf = 0; mf < 4; mf++) {
                int mr = warpM * 64 + mf * 16;
                a[mf][0] = *(const uint32_t*)(A + (mr + g)     * 128 + c0 + 4 * t);
                a[mf][1] = *(const uint32_t*)(A + (mr + 8 + g) * 128 + c0 + 4 * t);
                a[mf][2] = *(const uint32_t*)(A + (mr + g)     * 128 + c1 + 4 * t);
                a[mf][3] = *(const uint32_t*)(A + (mr + 8 + g) * 128 + c1 + 4 * t);
            }
            uint32_t b[4][2];
            #pragma unroll
            for (int nf = 0; nf < 4; nf++) {
                int nr = warpN * 32 + nf * 8 + g;
                b[nf][0] = *(const uint32_t*)(Bm + nr * 128 + c0 + 4 * t);
                b[nf][1] = *(const uint32_t*)(Bm + nr * 128 + c1 + 4 * t);
            }
            #pragma unroll
            for (int mf = 0; mf < 4; mf++)
                #pragma unroll
                for (int nf = 0; nf < 4; nf++)
                    mma_f16(acc[mf][nf], a[mf], b[nf][0], b[nf][1]);
        }
        __syncthreads();

        if (c + 2 < NCH) issue(c + 2, c & 1);
        CP_COMMIT();
    }

    // ---- epilogue ----
    #pragma unroll
    for (int mf = 0; mf < 4; mf++) {
        #pragma unroll
        for (int half = 0; half < 2; half++) {
            int gr = row0 + warpM * 64 + mf * 16 + g + half * 8;
            int bb = gr >> 11, n = gr & (SEQ - 1);
            #pragma unroll
            for (int nf = 0; nf < 4; nf++) {
                int gc = col0 + warpN * 32 + nf * 8 + t * 2;
                float v0 = acc[mf][nf][half * 2 + 0];
                float v1 = acc[mf][nf][half * 2 + 1];
                if (MODE == 0) {
                    int h = gc >> 6, d = gc & 63;
                    size_t bh = (size_t)(bb * NH + h);
                    if (z == 0) {
                        __half2 hv = __floats2half2_rn(v0 * 0.125f, v1 * 0.125f);
                        *(__half2*)&g_Qh[(bh * SEQ + n) * HD + d] = hv;
                    } else if (z == 1) {
                        __half2 hv = __floats2half2_rn(v0, v1);
                        *(__half2*)&g_Kh[(bh * SEQ + n) * HD + d] = hv;
                    } else {
                        g_VTh[(bh * HD + d)     * SEQ + n] = __float2half_rn(v0);
                        g_VTh[(bh * HD + d + 1) * SEQ + n] = __float2half_rn(v1);
                    }
                } else {
                    float2 bv = *(const float2*)&bias[gc];
                    *(float2*)&Cout[(size_t)gr * DM + gc]
                        = make_float2(v0 + bv.x, v1 + bv.y);
                }
            }
        }
    }
}

// ---------------------------------------------------------------------------
// Flash attention (causal) via fp16 m16n8k16 mma -- validated round 16.
// 64 queries/block, 128 threads. Zero-shuffle P handoff (C-frag == A-frag).
// cp.async 2-stage: stage s: K at bytes s*16384, VT at s*16384+8192.
// ---------------------------------------------------------------------------
__global__ __launch_bounds__(128, 3) void flash_mma()
{
    extern __shared__ __align__(16) uint32_t fsm[];

    const int tid  = threadIdx.x;
    const int lane = tid & 31;
    const int w    = tid >> 5;
    const int g    = lane >> 2;
    const int t    = lane & 3;

    const int qt = gridDim.x - 1 - blockIdx.x;
    const int h  = blockIdx.y;
    const int b  = blockIdx.z;
    const int q0 = qt * 64;
    const size_t bh = (size_t)(b * NH + h);

    const __half* Qh  = g_Qh  + bh * SEQ * HD;
    const __half* Kh  = g_Kh  + bh * SEQ * HD;
    const __half* VTh = g_VTh + bh * HD * SEQ;

    const int qrow0 = q0 + w * 16 + g;
    const int qrow1 = qrow0 + 8;

    const uint32_t base_u = smem_u32(fsm);
    const char* smc = (const char*)fsm;

    auto issue_tile = [&](int kt, int stage) {
        const int k0 = kt * 64;
        const int c  = tid & 7;
        const uint32_t k_u = base_u + stage * 16384;
        const uint32_t v_u = k_u + 8192;
        #pragma unroll
        for (int i = 0; i < 4; i++) {
            int rr = (tid >> 3) + i * 16;
            uint32_t off = (uint32_t)(rr * 128 + ((c ^ (rr & 7)) << 4));
            cp16(k_u + off, Kh  + (size_t)(k0 + rr) * HD + c * 8);
            cp16(v_u + off, VTh + (size_t)rr * SEQ + k0 + c * 8);
        }
    };

    uint32_t qf[4][4];
    #pragma unroll
    for (int kb = 0; kb < 4; kb++) {
        qf[kb][0] = *(const uint32_t*)(Qh + (size_t)qrow0 * HD + kb * 16 + 2 * t);
        qf[kb][1] = *(const uint32_t*)(Qh + (size_t)qrow1 * HD + kb * 16 + 2 * t);
        qf[kb][2] = *(const uint32_t*)(Qh + (size_t)qrow0 * HD + kb * 16 + 2 * t + 8);
        qf[kb][3] = *(const uint32_t*)(Qh + (size_t)qrow1 * HD + kb * 16 + 2 * t + 8);
    }

    float o[8][4] = {};
    float m0 = -1e30f, m1 = -1e30f;
    float l0 = 0.f, l1 = 0.f;

    const int ntiles = qt + 1;

    issue_tile(0, 0); CP_COMMIT();
    issue_tile(1, 1); CP_COMMIT();

    for (int kt = 0; kt < ntiles; kt++) {
        const int k0 = kt * 64;
        CP_WAIT1();
        __syncthreads();

        const char* sKc = smc + (kt & 1) * 16384;
        const char* sVc = sKc + 8192;

        float s[8][4] = {};
        #pragma unroll
        for (int kb = 0; kb < 4; kb++) {
            const int c0 = ((2 * kb)     << 4);
            const int c1 = ((2 * kb + 1) << 4);
            #pragma unroll
            for (int nf = 0; nf < 8; nf++) {
                int rb  = (nf * 8 + g) * 128 + 4 * t;
                int swz = (g << 4);
                uint32_t b0 = *(const uint32_t*)(sKc + rb + (c0 ^ swz));
                uint32_t b1 = *(const uint32_t*)(sKc + rb + (c1 ^ swz));
                mma_f16(s[nf], qf[kb], b0, b1);
            }
        }

        float mx0 = -1e30f, mx1 = -1e30f;
        if (k0 + 63 > qrow0) {
            #pragma unroll
            for (int nf = 0; nf < 8; nf++) {
                #pragma unroll
                for (int e = 0; e < 2; e++) {
                    int col = k0 + nf * 8 + 2 * t + e;
                    if (col > qrow0) s[nf][e]     = -1e30f;
                    if (col > qrow1) s[nf][2 + e] = -1e30f;
                    mx0 = fmaxf(mx0, s[nf][e]);
                    mx1 = fmaxf(mx1, s[nf][2 + e]);
                }
            }
        } else {
            #pragma unroll
            for (int nf = 0; nf < 8; nf++) {
                mx0 = fmaxf(mx0, fmaxf(s[nf][0], s[nf][1]));
                mx1 = fmaxf(mx1, fmaxf(s[nf][2], s[nf][3]));
            }
        }
        mx0 = fmaxf(mx0, __shfl_xor_sync(0xffffffffu, mx0, 1));
        mx0 = fmaxf(mx0, __shfl_xor_sync(0xffffffffu, mx0, 2));
        mx1 = fmaxf(mx1, __shfl_xor_sync(0xffffffffu, mx1, 1));
        mx1 = fmaxf(mx1, __shfl_xor_sync(0xffffffffu, mx1, 2));

        float nm0 = fmaxf(m0, mx0);
        float nm1 = fmaxf(m1, mx1);
        float c0s = __expf(m0 - nm0);
        float c1s = __expf(m1 - nm1);
        m0 = nm0; m1 = nm1;
        l0 *= c0s; l1 *= c1s;
        #pragma unroll
        for (int nf = 0; nf < 8; nf++) {
            o[nf][0] *= c0s; o[nf][1] *= c0s;
            o[nf][2] *= c1s; o[nf][3] *= c1s;
        }

        #pragma unroll
        for (int nf = 0; nf < 8; nf++) {
            float p0 = __expf(s[nf][0] - m0);
            float p1 = __expf(s[nf][1] - m0);
            float p2 = __expf(s[nf][2] - m1);
            float p3 = __expf(s[nf][3] - m1);
            s[nf][0] = p0; s[nf][1] = p1; s[nf][2] = p2; s[nf][3] = p3;
            l0 += p0 + p1;
            l1 += p2 + p3;
        }

        #pragma unroll
        for (int kb = 0; kb < 4; kb++) {
            uint32_t pa[4];
            pa[0] = packh2(s[2*kb][0],     s[2*kb][1]);
            pa[1] = packh2(s[2*kb][2],     s[2*kb][3]);
            pa[2] = packh2(s[2*kb + 1][0], s[2*kb + 1][1]);
            pa[3] = packh2(s[2*kb + 1][2], s[2*kb + 1][3]);

            const int c0 = ((2 * kb)     << 4);
            const int c1 = ((2 * kb + 1) << 4);
            #pragma unroll
            for (int nf = 0; nf < 8; nf++) {
                int rb  = (nf * 8 + g) * 128 + 4 * t;
                int swz = (g << 4);
                uint32_t b0 = *(const uint32_t*)(sVc + rb + (c0 ^ swz));
                uint32_t b1 = *(const uint32_t*)(sVc + rb + (c1 ^ swz));
                mma_f16(o[nf], pa, b0, b1);
            }
        }
        __syncthreads();

        if (kt + 2 < ntiles) issue_tile(kt + 2, kt & 1);
        CP_COMMIT();
    }

    // ---- finalize: ctx written as fp16 for the out GEMM ----
    l0 += __shfl_xor_sync(0xffffffffu, l0, 1);
    l0 += __shfl_xor_sync(0xffffffffu, l0, 2);
    l1 += __shfl_xor_sync(0xffffffffu, l1, 1);
    l1 += __shfl_xor_sync(0xffffffffu, l1, 2);
    const float inv0 = 1.f / l0;
    const float inv1 = 1.f / l1;

    #pragma unroll
    for (int nf = 0; nf < 8; nf++) {
        int dc = h * HD + nf * 8 + 2 * t;
        __half2 h0 = __floats2half2_rn(o[nf][0] * inv0, o[nf][1] * inv0);
        __half2 h1 = __floats2half2_rn(o[nf][2] * inv1, o[nf][3] * inv1);
        *(__half2*)&g_ctxh[(size_t)(b * SEQ + qrow0) * DM + dc] = h0;
        *(__half2*)&g_ctxh[(size_t)(b * SEQ + qrow1) * DM + dc] = h1;
    }
}

// ---------------------------------------------------------------------------
extern "C" void kernel_launch(void* const* d_in, const int* in_sizes, int n_in,
                              void* d_out, int out_size)
{
    const float* x  = (const float*)d_in[0];
    const float* Wq = (const float*)d_in[1];
    const float* Wk = (const float*)d_in[2];
    const float* Wv = (const float*)d_in[3];
    const float* Wo = (const float*)d_in[4];
    const float* bo = (const float*)d_in[5];
    float* out = (float*)d_out;

    cudaFuncSetAttribute(gemm_mma<0>, cudaFuncAttributeMaxDynamicSharedMemorySize, 65536);
    cudaFuncSetAttribute(gemm_mma<1>, cudaFuncAttributeMaxDynamicSharedMemorySize, 65536);
    cudaFuncSetAttribute(flash_mma,   cudaFuncAttributeMaxDynamicSharedMemorySize, 32768);

    cvt_x<<<1024, 256>>>(x);

    dim3 gt(32, 32, 4);
    transpose_w<<<gt, dim3(32, 8)>>>(Wq, Wk, Wv, Wo);

    dim3 g1(DM / 128, NTOK / 128, 3);      // 8 x 64 x 3
    gemm_mma<0><<<g1, 256, 65536>>>(nullptr, nullptr);

    dim3 g2(SEQ / 64, NH, B_);             // 32 x 16 x 4
    flash_mma<<<g2, 128, 32768>>>();

    dim3 g3(DM / 128, NTOK / 128);         // 8 x 64
    gemm_mma<1><<<g3, 256, 65536>>>(bo, out);
}